// round 2
// baseline (speedup 1.0000x reference)
#include <cuda_runtime.h>
#include <cuda_bf16.h>

#define N_NODES 10000
#define N_EDGES 320000
#define IN_DIM  128
#define HID     256
#define HID4    1024

// ---------------- scratch (static device globals; no allocation) ----------------
__device__ float g_Wsum[HID4 * HID];    // W_ih + W_hh            [4H, H]
__device__ float g_bsum[HID4];          // b_ih + b_hh            [4H]
__device__ float g_gates[HID * HID4];   // IW @ Wsum^T + bsum     [H, 4H]
__device__ float g_W[HID * HID];        // evolved GCN weight     [H, H]
__device__ float g_Wc[IN_DIM * HID];    // Wp @ W                 [IN, H]
__device__ float g_bc[HID];             // bp @ W                 [H]
__device__ float g_hw[N_NODES * HID];   // x @ Wc + bc            [N, H]
__device__ float g_dinv[N_NODES];       // deg -> rsqrt(deg)

// ---------------- tiny elementwise kernels ----------------
__global__ void k_wsum(const float* __restrict__ a, const float* __restrict__ b) {
    int t = blockIdx.x * blockDim.x + threadIdx.x;
    if (t < HID4 * HID) g_Wsum[t] = a[t] + b[t];
}

__global__ void k_bsum(const float* __restrict__ a, const float* __restrict__ b) {
    int t = blockIdx.x * blockDim.x + threadIdx.x;
    if (t < HID4) g_bsum[t] = a[t] + b[t];
}

__device__ __forceinline__ float sigf(float x) { return 1.0f / (1.0f + expf(-x)); }

// LSTM cell applied elementwise to evolve the weight matrix
__global__ void k_evolve(const float* __restrict__ iw) {
    int t = blockIdx.x * blockDim.x + threadIdx.x;   // t over H*H
    if (t >= HID * HID) return;
    int r = t >> 8;           // / HID
    int j = t & (HID - 1);    // % HID
    const float* gr = g_gates + r * HID4;
    float ig = sigf(gr[j]);
    float fg = sigf(gr[HID + j]);
    float gg = tanhf(gr[2 * HID + j]);
    float og = sigf(gr[3 * HID + j]);
    float c = fg * iw[t] + ig * gg;
    g_W[t] = og * tanhf(c);
}

// bc[j] = sum_k bp[k] * W[k, j]
__global__ void k_bc(const float* __restrict__ bp) {
    int j = threadIdx.x;
    float acc = 0.0f;
    #pragma unroll 8
    for (int k = 0; k < HID; k++) acc += bp[k] * g_W[k * HID + j];
    g_bc[j] = acc;
}

// ---------------- tiled fp32 GEMM: C[M,N] = A[M,K] @ op(B) (+bias per col) ----------------
// TB=false: B is [K,N] row-major. TB=true: B is [N,K] row-major (dot of rows).
// Requires: K % 16 == 0, N % 64 == 0. M arbitrary (guarded).
template<bool TB>
__global__ void sgemm(const float* __restrict__ A, const float* __restrict__ B,
                      const float* __restrict__ bias, float* __restrict__ C,
                      int M, int N, int K) {
    __shared__ float As[16][65];
    __shared__ float Bs[16][65];
    const int tx = threadIdx.x, ty = threadIdx.y;   // 16 x 16
    const int tid = ty * 16 + tx;
    const int row0 = blockIdx.y * 64;
    const int col0 = blockIdx.x * 64;

    float acc[4][4] = {};

    for (int kt = 0; kt < K; kt += 16) {
        // load A tile [64 rows][16 k]
        #pragma unroll
        for (int l = 0; l < 4; l++) {
            int idx = tid + l * 256;
            int r = idx >> 4, k = idx & 15;
            int row = row0 + r;
            As[k][r] = (row < M) ? A[row * K + kt + k] : 0.0f;
        }
        // load B tile [16 k][64 cols]
        if (!TB) {
            #pragma unroll
            for (int l = 0; l < 4; l++) {
                int idx = tid + l * 256;
                int k = idx >> 6, c = idx & 63;
                Bs[k][c] = B[(kt + k) * N + col0 + c];
            }
        } else {
            #pragma unroll
            for (int l = 0; l < 4; l++) {
                int idx = tid + l * 256;
                int c = idx >> 4, k = idx & 15;
                Bs[k][c] = B[(col0 + c) * K + kt + k];
            }
        }
        __syncthreads();

        #pragma unroll
        for (int k = 0; k < 16; k++) {
            float a[4], b[4];
            #pragma unroll
            for (int i = 0; i < 4; i++) a[i] = As[k][ty * 4 + i];
            #pragma unroll
            for (int j = 0; j < 4; j++) b[j] = Bs[k][tx * 4 + j];
            #pragma unroll
            for (int i = 0; i < 4; i++)
                #pragma unroll
                for (int j = 0; j < 4; j++)
                    acc[i][j] = fmaf(a[i], b[j], acc[i][j]);
        }
        __syncthreads();
    }

    #pragma unroll
    for (int i = 0; i < 4; i++) {
        int row = row0 + ty * 4 + i;
        if (row >= M) continue;
        #pragma unroll
        for (int j = 0; j < 4; j++) {
            int col = col0 + tx * 4 + j;
            float v = acc[i][j];
            if (bias) v += bias[col];
            C[row * N + col] = v;
        }
    }
}

// ---------------- graph propagation ----------------
__global__ void k_deg_init() {
    int t = blockIdx.x * blockDim.x + threadIdx.x;
    if (t < N_NODES) g_dinv[t] = 1.0f;   // self loop
}

__global__ void k_deg_acc(const int* __restrict__ ei) {
    int e = blockIdx.x * blockDim.x + threadIdx.x;
    if (e < N_EDGES) {
        int d = ei[N_EDGES + e];
        atomicAdd(&g_dinv[d], 1.0f);
    }
}

__global__ void k_dinv() {
    int t = blockIdx.x * blockDim.x + threadIdx.x;
    if (t < N_NODES) g_dinv[t] = rsqrtf(g_dinv[t]);
}

// out[i,:] = b_gcn + hw[i,:] * dinv[i]^2   (self-loop term + bias, init for scatter)
__global__ void k_out_init(const float* __restrict__ b_gcn, float* __restrict__ out) {
    int t = blockIdx.x * blockDim.x + threadIdx.x;
    if (t >= N_NODES * HID) return;
    int i = t >> 8;
    int j = t & (HID - 1);
    float di = g_dinv[i];
    out[t] = b_gcn[j] + g_hw[t] * di * di;
}

// one warp per edge: out[dst,:] += hw[src,:] * dinv[src]*dinv[dst]
__global__ void k_scatter(const int* __restrict__ ei, float* __restrict__ out) {
    int gw = (blockIdx.x * blockDim.x + threadIdx.x) >> 5;
    int lane = threadIdx.x & 31;
    if (gw >= N_EDGES) return;
    int s = ei[gw];
    int d = ei[N_EDGES + gw];
    float w = g_dinv[s] * g_dinv[d];
    const float4* hs = reinterpret_cast<const float4*>(g_hw + (long long)s * HID);
    float* od = out + (long long)d * HID;
    float4 v0 = hs[lane];
    float4 v1 = hs[lane + 32];
    int c0 = lane * 4;
    atomicAdd(od + c0 + 0, v0.x * w);
    atomicAdd(od + c0 + 1, v0.y * w);
    atomicAdd(od + c0 + 2, v0.z * w);
    atomicAdd(od + c0 + 3, v0.w * w);
    atomicAdd(od + 128 + c0 + 0, v1.x * w);
    atomicAdd(od + 128 + c0 + 1, v1.y * w);
    atomicAdd(od + 128 + c0 + 2, v1.z * w);
    atomicAdd(od + 128 + c0 + 3, v1.w * w);
}

// ---------------- launch ----------------
extern "C" void kernel_launch(void* const* d_in, const int* in_sizes, int n_in,
                              void* d_out, int out_size) {
    const float* x    = (const float*)d_in[0];
    const int*   ei   = (const int*)d_in[1];      // jax int64 is silently int32 (x64 disabled)
    const float* Wp   = (const float*)d_in[2];
    const float* bp   = (const float*)d_in[3];
    const float* W_ih = (const float*)d_in[4];
    const float* W_hh = (const float*)d_in[5];
    const float* b_ih = (const float*)d_in[6];
    const float* b_hh = (const float*)d_in[7];
    const float* IW   = (const float*)d_in[8];
    const float* bgcn = (const float*)d_in[9];
    float* out = (float*)d_out;

    float* d_Wsum;  cudaGetSymbolAddress((void**)&d_Wsum,  g_Wsum);
    float* d_bsum;  cudaGetSymbolAddress((void**)&d_bsum,  g_bsum);
    float* d_gates; cudaGetSymbolAddress((void**)&d_gates, g_gates);
    float* d_W;     cudaGetSymbolAddress((void**)&d_W,     g_W);
    float* d_Wc;    cudaGetSymbolAddress((void**)&d_Wc,    g_Wc);
    float* d_bc;    cudaGetSymbolAddress((void**)&d_bc,    g_bc);
    float* d_hw;    cudaGetSymbolAddress((void**)&d_hw,    g_hw);

    dim3 thr(16, 16);

    // 1) Wsum = W_ih + W_hh ; bsum = b_ih + b_hh
    k_wsum<<<(HID4 * HID + 255) / 256, 256>>>(W_ih, W_hh);
    k_bsum<<<(HID4 + 255) / 256, 256>>>(b_ih, b_hh);

    // 2) gates = IW @ Wsum^T + bsum     [H, 4H]
    sgemm<true><<<dim3(HID4 / 64, HID / 64), thr>>>(IW, d_Wsum, d_bsum, d_gates, HID, HID4, HID);

    // 3) W = LSTM-cell(gates, IW)
    k_evolve<<<(HID * HID + 255) / 256, 256>>>(IW);

    // 4) Wc = Wp @ W ; bc = bp @ W
    sgemm<false><<<dim3(HID / 64, IN_DIM / 64), thr>>>(Wp, d_W, nullptr, d_Wc, IN_DIM, HID, HID);
    k_bc<<<1, HID>>>(bp);

    // 5) hw = x @ Wc + bc      [N, H]   (fuses h = x@Wp+bp and hw = h@W)
    sgemm<false><<<dim3(HID / 64, (N_NODES + 63) / 64), thr>>>(x, d_Wc, d_bc, d_hw, N_NODES, HID, IN_DIM);

    // 6) degrees -> dinv
    k_deg_init<<<(N_NODES + 255) / 256, 256>>>();
    k_deg_acc<<<(N_EDGES + 255) / 256, 256>>>(ei);
    k_dinv<<<(N_NODES + 255) / 256, 256>>>();

    // 7) out = b_gcn + self-loop term, then edge scatter
    k_out_init<<<(N_NODES * HID + 255) / 256, 256>>>(bgcn, out);
    k_scatter<<<(N_EDGES * 32 + 255) / 256, 256>>>(ei, out);
}

// round 3
// speedup vs baseline: 2.0021x; 2.0021x over previous
#include <cuda_runtime.h>
#include <cuda_bf16.h>

#define N_NODES 10000
#define N_EDGES 320000
#define IN_DIM  128
#define HID     256
#define HID4    1024

// ---------------- scratch (static device globals; no allocation) ----------------
__device__ float g_Wsum[HID4 * HID];    // W_ih + W_hh            [4H, H]
__device__ float g_bsum[HID4];          // b_ih + b_hh            [4H]
__device__ float g_gates[HID * HID4];   // IW @ Wsum^T + bsum     [H, 4H]
__device__ float g_W[HID * HID];        // evolved GCN weight     [H, H]
__device__ float g_Wc[IN_DIM * HID];    // Wp @ W                 [IN, H]
__device__ float g_bc[HID];             // bp @ W                 [H]
__device__ float g_hw[N_NODES * HID];   // (x @ Wc + bc) * dinv   [N, H]  (pre-scaled)
__device__ float g_dinv[N_NODES];       // deg -> rsqrt(deg)

// ---------------- tiny elementwise kernels ----------------
__global__ void k_wsum(const float4* __restrict__ a, const float4* __restrict__ b) {
    int t = blockIdx.x * blockDim.x + threadIdx.x;
    if (t < HID4 * HID / 4) {
        float4 va = a[t], vb = b[t];
        reinterpret_cast<float4*>(g_Wsum)[t] =
            make_float4(va.x + vb.x, va.y + vb.y, va.z + vb.z, va.w + vb.w);
    }
}

__global__ void k_bsum(const float* __restrict__ a, const float* __restrict__ b) {
    int t = blockIdx.x * blockDim.x + threadIdx.x;
    if (t < HID4) g_bsum[t] = a[t] + b[t];
}

__device__ __forceinline__ float sigf(float x) { return 1.0f / (1.0f + expf(-x)); }

// LSTM cell applied elementwise to evolve the weight matrix
__global__ void k_evolve(const float* __restrict__ iw) {
    int t = blockIdx.x * blockDim.x + threadIdx.x;   // t over H*H
    if (t >= HID * HID) return;
    int r = t >> 8;
    int j = t & (HID - 1);
    const float* gr = g_gates + r * HID4;
    float ig = sigf(gr[j]);
    float fg = sigf(gr[HID + j]);
    float gg = tanhf(gr[2 * HID + j]);
    float og = sigf(gr[3 * HID + j]);
    float c = fg * iw[t] + ig * gg;
    g_W[t] = og * tanhf(c);
}

// bc[j] = sum_k bp[k] * W[k, j]
__global__ void k_bc(const float* __restrict__ bp) {
    int j = threadIdx.x;
    float acc = 0.0f;
    #pragma unroll 8
    for (int k = 0; k < HID; k++) acc += bp[k] * g_W[k * HID + j];
    g_bc[j] = acc;
}

// ---------------- tiled fp32 GEMM: C[M,N] = A[M,K] @ op(B) ----------------
// TB=false: B is [K,N] row-major. TB=true: B is [N,K] row-major.
// EPI=0: C = AB (+bias). EPI=1: v = (AB+bias)*dinv[row]; C = v; C2 = v.
// Requires: K % 16 == 0, N % 64 == 0, K % 4 == 0.
template<bool TB, int EPI>
__global__ void sgemm(const float* __restrict__ A, const float* __restrict__ B,
                      const float* __restrict__ bias, float* __restrict__ C,
                      float* __restrict__ C2,
                      int M, int N, int K) {
    __shared__ float As[16][68];
    __shared__ float Bs[16][68];
    const int tx = threadIdx.x, ty = threadIdx.y;   // 16 x 16
    const int tid = ty * 16 + tx;
    const int row0 = blockIdx.y * 64;
    const int col0 = blockIdx.x * 64;

    float acc[4][4] = {};

    for (int kt = 0; kt < K; kt += 16) {
        // load A tile [64 rows][16 k] — one float4 per thread along K
        {
            int r = tid >> 2;          // 0..63
            int kq = (tid & 3) * 4;    // 0,4,8,12
            int row = row0 + r;
            float4 v = (row < M) ? *reinterpret_cast<const float4*>(A + (size_t)row * K + kt + kq)
                                 : make_float4(0.f, 0.f, 0.f, 0.f);
            As[kq + 0][r] = v.x;
            As[kq + 1][r] = v.y;
            As[kq + 2][r] = v.z;
            As[kq + 3][r] = v.w;
        }
        // load B tile [16 k][64 cols]
        if (!TB) {
            int k = tid >> 4;          // 0..15
            int cq = (tid & 15) * 4;   // 0..60
            float4 v = *reinterpret_cast<const float4*>(B + (size_t)(kt + k) * N + col0 + cq);
            *reinterpret_cast<float4*>(&Bs[k][cq]) = v;
        } else {
            int c = tid >> 2;          // 0..63
            int kq = (tid & 3) * 4;
            float4 v = *reinterpret_cast<const float4*>(B + (size_t)(col0 + c) * K + kt + kq);
            Bs[kq + 0][c] = v.x;
            Bs[kq + 1][c] = v.y;
            Bs[kq + 2][c] = v.z;
            Bs[kq + 3][c] = v.w;
        }
        __syncthreads();

        #pragma unroll
        for (int k = 0; k < 16; k++) {
            float4 a = *reinterpret_cast<const float4*>(&As[k][ty * 4]);
            float4 b = *reinterpret_cast<const float4*>(&Bs[k][tx * 4]);
            float av[4] = {a.x, a.y, a.z, a.w};
            float bv[4] = {b.x, b.y, b.z, b.w};
            #pragma unroll
            for (int i = 0; i < 4; i++)
                #pragma unroll
                for (int j = 0; j < 4; j++)
                    acc[i][j] = fmaf(av[i], bv[j], acc[i][j]);
        }
        __syncthreads();
    }

    #pragma unroll
    for (int i = 0; i < 4; i++) {
        int row = row0 + ty * 4 + i;
        if (row >= M) continue;
        float scale = (EPI == 1) ? g_dinv[row] : 1.0f;
        int col = col0 + tx * 4;
        float4 v;
        v.x = acc[i][0]; v.y = acc[i][1]; v.z = acc[i][2]; v.w = acc[i][3];
        if (bias) {
            const float4 bb = *reinterpret_cast<const float4*>(bias + col);
            v.x += bb.x; v.y += bb.y; v.z += bb.z; v.w += bb.w;
        }
        if (EPI == 1) { v.x *= scale; v.y *= scale; v.z *= scale; v.w *= scale; }
        *reinterpret_cast<float4*>(C + (size_t)row * N + col) = v;
        if (EPI == 1)
            *reinterpret_cast<float4*>(C2 + (size_t)row * N + col) = v;
    }
}

// ---------------- graph propagation ----------------
__global__ void k_deg_init() {
    int t = blockIdx.x * blockDim.x + threadIdx.x;
    if (t < N_NODES) g_dinv[t] = 1.0f;   // self loop
}

__global__ void k_deg_acc(const int* __restrict__ ei) {
    int e = blockIdx.x * blockDim.x + threadIdx.x;
    if (e < N_EDGES) atomicAdd(&g_dinv[ei[N_EDGES + e]], 1.0f);
}

__global__ void k_dinv() {
    int t = blockIdx.x * blockDim.x + threadIdx.x;
    if (t < N_NODES) g_dinv[t] = rsqrtf(g_dinv[t]);
}

// one warp per edge: out[dst,:] += hw'[src,:]   (hw' pre-scaled by dinv[src])
__global__ void k_scatter(const int* __restrict__ ei, float* __restrict__ out) {
    int gw = (blockIdx.x * blockDim.x + threadIdx.x) >> 5;
    int lane = threadIdx.x & 31;
    if (gw >= N_EDGES) return;
    int s = ei[gw];
    int d = ei[N_EDGES + gw];
    const float4* hs = reinterpret_cast<const float4*>(g_hw + (size_t)s * HID);
    float4* od = reinterpret_cast<float4*>(out + (size_t)d * HID);
    float4 v0 = hs[lane];
    float4 v1 = hs[lane + 32];
    asm volatile("red.global.add.v4.f32 [%0], {%1,%2,%3,%4};"
                 :: "l"(od + lane), "f"(v0.x), "f"(v0.y), "f"(v0.z), "f"(v0.w) : "memory");
    asm volatile("red.global.add.v4.f32 [%0], {%1,%2,%3,%4};"
                 :: "l"(od + lane + 32), "f"(v1.x), "f"(v1.y), "f"(v1.z), "f"(v1.w) : "memory");
}

// out = out * dinv[i] + b_gcn   (folds the deferred dst normalization + bias)
__global__ void k_finalize(const float* __restrict__ b_gcn, float* __restrict__ out) {
    int t = blockIdx.x * blockDim.x + threadIdx.x;   // over N*H/4
    if (t >= N_NODES * HID / 4) return;
    int i = t >> 6;            // node
    int jq = (t & 63);         // float4 col
    float di = g_dinv[i];
    float4 v = reinterpret_cast<float4*>(out)[t];
    const float4 b = reinterpret_cast<const float4*>(b_gcn)[jq];
    v.x = v.x * di + b.x;
    v.y = v.y * di + b.y;
    v.z = v.z * di + b.z;
    v.w = v.w * di + b.w;
    reinterpret_cast<float4*>(out)[t] = v;
}

// ---------------- launch ----------------
extern "C" void kernel_launch(void* const* d_in, const int* in_sizes, int n_in,
                              void* d_out, int out_size) {
    const float* x    = (const float*)d_in[0];
    const int*   ei   = (const int*)d_in[1];      // jax int64 is silently int32 (x64 disabled)
    const float* Wp   = (const float*)d_in[2];
    const float* bp   = (const float*)d_in[3];
    const float* W_ih = (const float*)d_in[4];
    const float* W_hh = (const float*)d_in[5];
    const float* b_ih = (const float*)d_in[6];
    const float* b_hh = (const float*)d_in[7];
    const float* IW   = (const float*)d_in[8];
    const float* bgcn = (const float*)d_in[9];
    float* out = (float*)d_out;

    float* d_Wsum;  cudaGetSymbolAddress((void**)&d_Wsum,  g_Wsum);
    float* d_bsum;  cudaGetSymbolAddress((void**)&d_bsum,  g_bsum);
    float* d_gates; cudaGetSymbolAddress((void**)&d_gates, g_gates);
    float* d_W;     cudaGetSymbolAddress((void**)&d_W,     g_W);
    float* d_Wc;    cudaGetSymbolAddress((void**)&d_Wc,    g_Wc);
    float* d_bc;    cudaGetSymbolAddress((void**)&d_bc,    g_bc);
    float* d_hw;    cudaGetSymbolAddress((void**)&d_hw,    g_hw);

    dim3 thr(16, 16);

    // degrees -> dinv (needed by main GEMM epilogue)
    k_deg_init<<<(N_NODES + 255) / 256, 256>>>();
    k_deg_acc<<<(N_EDGES + 255) / 256, 256>>>(ei);
    k_dinv<<<(N_NODES + 255) / 256, 256>>>();

    // weight evolution chain
    k_wsum<<<(HID4 * HID / 4 + 255) / 256, 256>>>((const float4*)W_ih, (const float4*)W_hh);
    k_bsum<<<(HID4 + 255) / 256, 256>>>(b_ih, b_hh);
    sgemm<true, 0><<<dim3(HID4 / 64, HID / 64), thr>>>(IW, d_Wsum, d_bsum, d_gates, nullptr, HID, HID4, HID);
    k_evolve<<<(HID * HID + 255) / 256, 256>>>(IW);
    sgemm<false, 0><<<dim3(HID / 64, IN_DIM / 64), thr>>>(Wp, d_W, nullptr, d_Wc, nullptr, IN_DIM, HID, HID);
    k_bc<<<1, HID>>>(bp);

    // hw' = (x @ Wc + bc) * dinv[row]; out initialized with hw' (self-loop term)
    sgemm<false, 1><<<dim3(HID / 64, (N_NODES + 63) / 64), thr>>>(x, d_Wc, d_bc, d_hw, out, N_NODES, HID, IN_DIM);

    // edge scatter: out[d] += hw'[s]
    k_scatter<<<(N_EDGES * 32 + 255) / 256, 256>>>(ei, out);

    // out = out * dinv + b_gcn
    k_finalize<<<(N_NODES * HID / 4 + 255) / 256, 256>>>(bgcn, out);
}

// round 4
// speedup vs baseline: 2.1167x; 1.0573x over previous
#include <cuda_runtime.h>
#include <cuda_bf16.h>

#define N_NODES 10000
#define N_EDGES 320000
#define IN_DIM  128
#define HID     256
#define HID4    1024

// ---------------- scratch (static device globals; no allocation) ----------------
__device__ float g_gates[HID * HID4];   // IW @ (W_ih+W_hh)^T + b_ih + b_hh   [H, 4H]
__device__ float g_W[HID * HID];        // evolved GCN weight                 [H, H]
__device__ float g_Wc[IN_DIM * HID];    // Wp @ W                             [IN, H]
__device__ float g_bc[HID];             // bp @ W                             [H]
__device__ float g_hw[N_NODES * HID];   // (x @ Wc + bc) * dinv[row]          [N, H]
__device__ float g_dinv[N_NODES];       // rsqrt(deg+1)
__device__ int   g_deg[N_NODES];        // in-degree (excl. self loop)
__device__ int   g_off[N_NODES + 1];    // CSR row offsets (by dst)
__device__ int   g_cur[N_NODES];        // fill cursors
__device__ int   g_csr[N_EDGES];        // src indices grouped by dst

// ---------------- CSR build ----------------
__global__ void k_deg_zero() {
    int t = blockIdx.x * blockDim.x + threadIdx.x;
    if (t < N_NODES) g_deg[t] = 0;
}

__global__ void k_deg_acc(const int* __restrict__ ei) {
    int e = blockIdx.x * blockDim.x + threadIdx.x;
    if (e < N_EDGES) atomicAdd(&g_deg[ei[N_EDGES + e]], 1);
}

// single-block scan over 10000 degrees (16 per thread, 1024 threads)
__global__ void k_scan() {
    __shared__ int part[1024];
    const int t = threadIdx.x;
    const int base = t * 16;
    int local[16];
    int sum = 0;
    #pragma unroll
    for (int j = 0; j < 16; j++) {
        int n = base + j;
        int d = (n < N_NODES) ? g_deg[n] : 0;
        local[j] = sum;
        sum += d;
    }
    part[t] = sum;
    __syncthreads();
    // Hillis-Steele inclusive scan
    #pragma unroll
    for (int o = 1; o < 1024; o <<= 1) {
        int v = (t >= o) ? part[t - o] : 0;
        __syncthreads();
        part[t] += v;
        __syncthreads();
    }
    int pre = (t > 0) ? part[t - 1] : 0;
    #pragma unroll
    for (int j = 0; j < 16; j++) {
        int n = base + j;
        if (n < N_NODES) {
            int o = pre + local[j];
            g_off[n] = o;
            g_cur[n] = o;
            g_dinv[n] = rsqrtf((float)g_deg[n] + 1.0f);
        }
    }
    if (t == 1023) g_off[N_NODES] = part[1023];
}

__global__ void k_fill(const int* __restrict__ ei) {
    int e = blockIdx.x * blockDim.x + threadIdx.x;
    if (e >= N_EDGES) return;
    int s = ei[e];
    int d = ei[N_EDGES + e];
    int pos = atomicAdd(&g_cur[d], 1);
    g_csr[pos] = s;
}

// ---------------- weight-evolution elementwise ----------------
__device__ __forceinline__ float sigf(float x) { return 1.0f / (1.0f + expf(-x)); }

__global__ void k_evolve(const float* __restrict__ iw) {
    int t = blockIdx.x * blockDim.x + threadIdx.x;   // over H*H
    if (t >= HID * HID) return;
    int r = t >> 8;
    int j = t & (HID - 1);
    const float* gr = g_gates + r * HID4;
    float ig = sigf(gr[j]);
    float fg = sigf(gr[HID + j]);
    float gg = tanhf(gr[2 * HID + j]);
    float og = sigf(gr[3 * HID + j]);
    float c = fg * iw[t] + ig * gg;
    g_W[t] = og * tanhf(c);
}

// bc[j] = sum_k bp[k] * W[k, j]
__global__ void k_bc(const float* __restrict__ bp) {
    int j = threadIdx.x;
    float acc = 0.0f;
    #pragma unroll 8
    for (int k = 0; k < HID; k++) acc += bp[k] * g_W[k * HID + j];
    g_bc[j] = acc;
}

// ---------------- tiled fp32 GEMM ----------------
// C[M,N] = A[M,K] @ op(B [+ B2]) + bias [+ bias2], optionally scaled by dinv[row].
// TB=false: B is [K,N]. TB=true: B is [N,K]. Requires K%16==0, N%64==0.
template<bool TB, bool FUSEB, bool SCALE>
__global__ void sgemm(const float* __restrict__ A, const float* __restrict__ B,
                      const float* __restrict__ B2,
                      const float* __restrict__ bias, const float* __restrict__ bias2,
                      float* __restrict__ C, int M, int N, int K) {
    __shared__ float As[16][68];
    __shared__ float Bs[16][68];
    const int tx = threadIdx.x, ty = threadIdx.y;   // 16 x 16
    const int tid = ty * 16 + tx;
    const int row0 = blockIdx.y * 64;
    const int col0 = blockIdx.x * 64;

    float acc[4][4] = {};

    for (int kt = 0; kt < K; kt += 16) {
        {   // A tile [64 rows][16 k]
            int r = tid >> 2;
            int kq = (tid & 3) * 4;
            int row = row0 + r;
            float4 v = (row < M) ? *reinterpret_cast<const float4*>(A + (size_t)row * K + kt + kq)
                                 : make_float4(0.f, 0.f, 0.f, 0.f);
            As[kq + 0][r] = v.x; As[kq + 1][r] = v.y;
            As[kq + 2][r] = v.z; As[kq + 3][r] = v.w;
        }
        if (!TB) {  // B tile [16 k][64 cols]
            int k = tid >> 4;
            int cq = (tid & 15) * 4;
            size_t idx = (size_t)(kt + k) * N + col0 + cq;
            float4 v = *reinterpret_cast<const float4*>(B + idx);
            if (FUSEB) {
                float4 w = *reinterpret_cast<const float4*>(B2 + idx);
                v.x += w.x; v.y += w.y; v.z += w.z; v.w += w.w;
            }
            *reinterpret_cast<float4*>(&Bs[k][cq]) = v;
        } else {
            int c = tid >> 2;
            int kq = (tid & 3) * 4;
            size_t idx = (size_t)(col0 + c) * K + kt + kq;
            float4 v = *reinterpret_cast<const float4*>(B + idx);
            if (FUSEB) {
                float4 w = *reinterpret_cast<const float4*>(B2 + idx);
                v.x += w.x; v.y += w.y; v.z += w.z; v.w += w.w;
            }
            Bs[kq + 0][c] = v.x; Bs[kq + 1][c] = v.y;
            Bs[kq + 2][c] = v.z; Bs[kq + 3][c] = v.w;
        }
        __syncthreads();

        #pragma unroll
        for (int k = 0; k < 16; k++) {
            float4 a = *reinterpret_cast<const float4*>(&As[k][ty * 4]);
            float4 b = *reinterpret_cast<const float4*>(&Bs[k][tx * 4]);
            float av[4] = {a.x, a.y, a.z, a.w};
            float bv[4] = {b.x, b.y, b.z, b.w};
            #pragma unroll
            for (int i = 0; i < 4; i++)
                #pragma unroll
                for (int j = 0; j < 4; j++)
                    acc[i][j] = fmaf(av[i], bv[j], acc[i][j]);
        }
        __syncthreads();
    }

    #pragma unroll
    for (int i = 0; i < 4; i++) {
        int row = row0 + ty * 4 + i;
        if (row >= M) continue;
        float scale = SCALE ? g_dinv[row] : 1.0f;
        int col = col0 + tx * 4;
        float4 v = make_float4(acc[i][0], acc[i][1], acc[i][2], acc[i][3]);
        if (bias) {
            const float4 bb = *reinterpret_cast<const float4*>(bias + col);
            v.x += bb.x; v.y += bb.y; v.z += bb.z; v.w += bb.w;
        }
        if (bias2) {
            const float4 bb = *reinterpret_cast<const float4*>(bias2 + col);
            v.x += bb.x; v.y += bb.y; v.z += bb.z; v.w += bb.w;
        }
        if (SCALE) { v.x *= scale; v.y *= scale; v.z *= scale; v.w *= scale; }
        *reinterpret_cast<float4*>(C + (size_t)row * N + col) = v;
    }
}

// ---------------- gather aggregation: one warp per dst node ----------------
// out[i,:] = ( hw'[i,:] + sum_{e: dst=i} hw'[src_e,:] ) * dinv[i] + b_gcn
__global__ void k_gather(const float* __restrict__ b_gcn, float* __restrict__ out) {
    int w = (blockIdx.x * blockDim.x + threadIdx.x) >> 5;
    int lane = threadIdx.x & 31;
    if (w >= N_NODES) return;

    const int beg = g_off[w];
    const int end = g_off[w + 1];

    const float4* self = reinterpret_cast<const float4*>(g_hw + (size_t)w * HID);
    float4 a0 = self[lane];
    float4 a1 = self[lane + 32];

    for (int c = beg; c < end; c += 32) {
        int n = min(32, end - c);
        int idx = (c + lane < end) ? g_csr[c + lane] : 0;
        for (int j = 0; j < n; j++) {
            int s = __shfl_sync(0xffffffffu, idx, j);
            const float4* hs = reinterpret_cast<const float4*>(g_hw + (size_t)s * HID);
            float4 v0 = hs[lane];
            float4 v1 = hs[lane + 32];
            a0.x += v0.x; a0.y += v0.y; a0.z += v0.z; a0.w += v0.w;
            a1.x += v1.x; a1.y += v1.y; a1.z += v1.z; a1.w += v1.w;
        }
    }

    float di = g_dinv[w];
    const float4 b0 = reinterpret_cast<const float4*>(b_gcn)[lane];
    const float4 b1 = reinterpret_cast<const float4*>(b_gcn)[lane + 32];
    float4 o0, o1;
    o0.x = a0.x * di + b0.x; o0.y = a0.y * di + b0.y;
    o0.z = a0.z * di + b0.z; o0.w = a0.w * di + b0.w;
    o1.x = a1.x * di + b1.x; o1.y = a1.y * di + b1.y;
    o1.z = a1.z * di + b1.z; o1.w = a1.w * di + b1.w;
    float4* od = reinterpret_cast<float4*>(out + (size_t)w * HID);
    od[lane] = o0;
    od[lane + 32] = o1;
}

// ---------------- launch ----------------
extern "C" void kernel_launch(void* const* d_in, const int* in_sizes, int n_in,
                              void* d_out, int out_size) {
    const float* x    = (const float*)d_in[0];
    const int*   ei   = (const int*)d_in[1];      // jax int64 is silently int32 (x64 disabled)
    const float* Wp   = (const float*)d_in[2];
    const float* bp   = (const float*)d_in[3];
    const float* W_ih = (const float*)d_in[4];
    const float* W_hh = (const float*)d_in[5];
    const float* b_ih = (const float*)d_in[6];
    const float* b_hh = (const float*)d_in[7];
    const float* IW   = (const float*)d_in[8];
    const float* bgcn = (const float*)d_in[9];
    float* out = (float*)d_out;

    float* d_gates; cudaGetSymbolAddress((void**)&d_gates, g_gates);
    float* d_W;     cudaGetSymbolAddress((void**)&d_W,     g_W);
    float* d_Wc;    cudaGetSymbolAddress((void**)&d_Wc,    g_Wc);
    float* d_bc;    cudaGetSymbolAddress((void**)&d_bc,    g_bc);
    float* d_hw;    cudaGetSymbolAddress((void**)&d_hw,    g_hw);

    dim3 thr(16, 16);

    // CSR build + dinv
    k_deg_zero<<<(N_NODES + 255) / 256, 256>>>();
    k_deg_acc<<<(N_EDGES + 255) / 256, 256>>>(ei);
    k_scan<<<1, 1024>>>();
    k_fill<<<(N_EDGES + 255) / 256, 256>>>(ei);

    // gates = IW @ (W_ih + W_hh)^T + (b_ih + b_hh)
    sgemm<true, true, false><<<dim3(HID4 / 64, HID / 64), thr>>>(
        IW, W_ih, W_hh, b_ih, b_hh, d_gates, HID, HID4, HID);
    k_evolve<<<(HID * HID + 255) / 256, 256>>>(IW);

    // Wc = Wp @ W ; bc = bp @ W
    sgemm<false, false, false><<<dim3(HID / 64, IN_DIM / 64), thr>>>(
        Wp, d_W, nullptr, nullptr, nullptr, d_Wc, IN_DIM, HID, HID);
    k_bc<<<1, HID>>>(bp);

    // hw' = (x @ Wc + bc) * dinv[row]
    sgemm<false, false, true><<<dim3(HID / 64, (N_NODES + 63) / 64), thr>>>(
        x, d_Wc, nullptr, d_bc, nullptr, d_hw, N_NODES, HID, IN_DIM);

    // out[i] = (hw'[i] + sum_in hw'[s]) * dinv[i] + b_gcn
    k_gather<<<(N_NODES * 32 + 255) / 256, 256>>>(bgcn, out);
}

// round 5
// speedup vs baseline: 2.4463x; 1.1557x over previous
#include <cuda_runtime.h>
#include <cuda_bf16.h>

#define N_NODES 10000
#define N_EDGES 320000
#define IN_DIM  128
#define HID     256
#define HID4    1024

// ---------------- scratch (static device globals; no allocation) ----------------
__device__ float g_gates[HID * HID4];   // IW @ (W_ih+W_hh)^T + b_ih + b_hh   [H, 4H]
__device__ float g_W[HID * HID];        // evolved GCN weight                 [H, H]
__device__ float g_Wc[IN_DIM * HID];    // Wp @ W                             [IN, H]
__device__ float g_bc[HID];             // bp @ W                             [H]
__device__ float g_y[N_NODES * IN_DIM]; // aggregated scaled features        [N, IN]
__device__ float g_u[N_NODES];          // (dinv[i] + sum dinv[s]) * dinv[i]
__device__ float g_dinv[N_NODES];       // rsqrt(deg+1)
__device__ int   g_deg[N_NODES];
__device__ int   g_off[N_NODES + 1];    // CSR row offsets (by dst)
__device__ int   g_cur[N_NODES];
__device__ int   g_csr[N_EDGES];        // src indices grouped by dst

// ---------------- CSR build ----------------
__global__ void k_deg_zero() {
    int t = blockIdx.x * blockDim.x + threadIdx.x;
    if (t < N_NODES) g_deg[t] = 0;
}

__global__ void k_deg_acc(const int* __restrict__ ei) {
    int e = blockIdx.x * blockDim.x + threadIdx.x;
    if (e < N_EDGES) atomicAdd(&g_deg[ei[N_EDGES + e]], 1);
}

// single-block scan over 10000 degrees (16 per thread, 1024 threads)
__global__ void k_scan() {
    __shared__ int part[1024];
    const int t = threadIdx.x;
    const int base = t * 16;
    int local[16];
    int sum = 0;
    #pragma unroll
    for (int j = 0; j < 16; j++) {
        int n = base + j;
        int d = (n < N_NODES) ? g_deg[n] : 0;
        local[j] = sum;
        sum += d;
    }
    part[t] = sum;
    __syncthreads();
    #pragma unroll
    for (int o = 1; o < 1024; o <<= 1) {
        int v = (t >= o) ? part[t - o] : 0;
        __syncthreads();
        part[t] += v;
        __syncthreads();
    }
    int pre = (t > 0) ? part[t - 1] : 0;
    #pragma unroll
    for (int j = 0; j < 16; j++) {
        int n = base + j;
        if (n < N_NODES) {
            int o = pre + local[j];
            g_off[n] = o;
            g_cur[n] = o;
            g_dinv[n] = rsqrtf((float)g_deg[n] + 1.0f);
        }
    }
    if (t == 1023) g_off[N_NODES] = part[1023];
}

__global__ void k_fill(const int* __restrict__ ei) {
    int e = blockIdx.x * blockDim.x + threadIdx.x;
    if (e >= N_EDGES) return;
    int s = ei[e];
    int d = ei[N_EDGES + e];
    int pos = atomicAdd(&g_cur[d], 1);
    g_csr[pos] = s;
}

// ---------------- weight-evolution elementwise ----------------
__device__ __forceinline__ float tanh_fast(float x) {
    float r;
    asm("tanh.approx.f32 %0, %1;" : "=f"(r) : "f"(x));
    return r;
}
__device__ __forceinline__ float sig_fast(float x) {
    return 0.5f * tanh_fast(0.5f * x) + 0.5f;
}

__global__ void k_evolve(const float* __restrict__ iw) {
    int t = blockIdx.x * blockDim.x + threadIdx.x;   // over H*H
    if (t >= HID * HID) return;
    int r = t >> 8;
    int j = t & (HID - 1);
    const float* gr = g_gates + r * HID4;
    float ig = sig_fast(gr[j]);
    float fg = sig_fast(gr[HID + j]);
    float gg = tanh_fast(gr[2 * HID + j]);
    float og = sig_fast(gr[3 * HID + j]);
    float c = fg * iw[t] + ig * gg;
    g_W[t] = og * tanh_fast(c);
}

// bc[j] = sum_k bp[k] * W[k, j]   (4 blocks x 256 threads)
__global__ void k_bc(const float* __restrict__ bp) {
    __shared__ float red[4][64];
    int c  = threadIdx.x & 63;
    int kk = threadIdx.x >> 6;      // 0..3
    int col = blockIdx.x * 64 + c;
    float acc = 0.0f;
    for (int k = kk; k < HID; k += 4) acc += bp[k] * g_W[k * HID + col];
    red[kk][c] = acc;
    __syncthreads();
    if (kk == 0) g_bc[col] = red[0][c] + red[1][c] + red[2][c] + red[3][c];
}

// ---------------- small tiled fp32 GEMM (weight chain) ----------------
// C[M,N] = A[M,K] @ op(B [+ B2]) + bias [+ bias2].
// TB=false: B is [K,N]. TB=true: B is [N,K]. Requires K%16==0, N%64==0.
template<bool TB, bool FUSEB>
__global__ void sgemm(const float* __restrict__ A, const float* __restrict__ B,
                      const float* __restrict__ B2,
                      const float* __restrict__ bias, const float* __restrict__ bias2,
                      float* __restrict__ C, int M, int N, int K) {
    __shared__ float As[16][68];
    __shared__ float Bs[16][68];
    const int tx = threadIdx.x, ty = threadIdx.y;
    const int tid = ty * 16 + tx;
    const int row0 = blockIdx.y * 64;
    const int col0 = blockIdx.x * 64;

    float acc[4][4] = {};

    for (int kt = 0; kt < K; kt += 16) {
        {
            int r = tid >> 2;
            int kq = (tid & 3) * 4;
            int row = row0 + r;
            float4 v = (row < M) ? *reinterpret_cast<const float4*>(A + (size_t)row * K + kt + kq)
                                 : make_float4(0.f, 0.f, 0.f, 0.f);
            As[kq + 0][r] = v.x; As[kq + 1][r] = v.y;
            As[kq + 2][r] = v.z; As[kq + 3][r] = v.w;
        }
        if (!TB) {
            int k = tid >> 4;
            int cq = (tid & 15) * 4;
            size_t idx = (size_t)(kt + k) * N + col0 + cq;
            float4 v = *reinterpret_cast<const float4*>(B + idx);
            if (FUSEB) {
                float4 w = *reinterpret_cast<const float4*>(B2 + idx);
                v.x += w.x; v.y += w.y; v.z += w.z; v.w += w.w;
            }
            *reinterpret_cast<float4*>(&Bs[k][cq]) = v;
        } else {
            int c = tid >> 2;
            int kq = (tid & 3) * 4;
            size_t idx = (size_t)(col0 + c) * K + kt + kq;
            float4 v = *reinterpret_cast<const float4*>(B + idx);
            if (FUSEB) {
                float4 w = *reinterpret_cast<const float4*>(B2 + idx);
                v.x += w.x; v.y += w.y; v.z += w.z; v.w += w.w;
            }
            Bs[kq + 0][c] = v.x; Bs[kq + 1][c] = v.y;
            Bs[kq + 2][c] = v.z; Bs[kq + 3][c] = v.w;
        }
        __syncthreads();

        #pragma unroll
        for (int k = 0; k < 16; k++) {
            float4 a = *reinterpret_cast<const float4*>(&As[k][ty * 4]);
            float4 b = *reinterpret_cast<const float4*>(&Bs[k][tx * 4]);
            float av[4] = {a.x, a.y, a.z, a.w};
            float bv[4] = {b.x, b.y, b.z, b.w};
            #pragma unroll
            for (int i = 0; i < 4; i++)
                #pragma unroll
                for (int j = 0; j < 4; j++)
                    acc[i][j] = fmaf(av[i], bv[j], acc[i][j]);
        }
        __syncthreads();
    }

    #pragma unroll
    for (int i = 0; i < 4; i++) {
        int row = row0 + ty * 4 + i;
        if (row >= M) continue;
        int col = col0 + tx * 4;
        float4 v = make_float4(acc[i][0], acc[i][1], acc[i][2], acc[i][3]);
        if (bias) {
            const float4 bb = *reinterpret_cast<const float4*>(bias + col);
            v.x += bb.x; v.y += bb.y; v.z += bb.z; v.w += bb.w;
        }
        if (bias2) {
            const float4 bb = *reinterpret_cast<const float4*>(bias2 + col);
            v.x += bb.x; v.y += bb.y; v.z += bb.z; v.w += bb.w;
        }
        *reinterpret_cast<float4*>(C + (size_t)row * N + col) = v;
    }
}

// ---------------- gather aggregation on 128-dim x: one warp per dst node ----------------
// y[i,:] = x[i,:]*dinv[i] + sum_{s in N(i)} x[s,:]*dinv[s]
// u[i]   = (dinv[i] + sum dinv[s]) * dinv[i]
__global__ void k_gather(const float* __restrict__ x) {
    int w = (blockIdx.x * blockDim.x + threadIdx.x) >> 5;
    int lane = threadIdx.x & 31;
    if (w >= N_NODES) return;

    const int beg = g_off[w];
    const int end = g_off[w + 1];
    const float4* x4 = reinterpret_cast<const float4*>(x);

    float di = g_dinv[w];
    float4 xv = x4[(size_t)w * 32 + lane];
    float4 acc = make_float4(xv.x * di, xv.y * di, xv.z * di, xv.w * di);
    float tsum = di;

    for (int c = beg; c < end; c += 32) {
        int n = min(32, end - c);
        int idx = 0;
        float dv = 0.0f;
        if (c + lane < end) {
            idx = g_csr[c + lane];
            dv = g_dinv[idx];
        }
        for (int j = 0; j < n; j++) {
            int s = __shfl_sync(0xffffffffu, idx, j);
            float ws = __shfl_sync(0xffffffffu, dv, j);
            float4 v = x4[(size_t)s * 32 + lane];
            acc.x = fmaf(v.x, ws, acc.x);
            acc.y = fmaf(v.y, ws, acc.y);
            acc.z = fmaf(v.z, ws, acc.z);
            acc.w = fmaf(v.w, ws, acc.w);
            tsum += ws;
        }
    }

    reinterpret_cast<float4*>(g_y)[(size_t)w * 32 + lane] = acc;
    if (lane == 0) g_u[w] = tsum * di;
}

// ---------------- main GEMM: out[N_NODES, HID] = (y @ Wc)*dinv + bc*u + bgcn ----------------
// 128x64 tiles, 8x4 micro-tiles, K = IN_DIM = 128.
__global__ void k_main_gemm(const float* __restrict__ bgcn, float* __restrict__ out) {
    __shared__ float As[16][132];
    __shared__ float Bs[16][68];
    const int tid = threadIdx.x;           // 256 threads
    const int tx = tid & 15;               // col group
    const int ty = tid >> 4;               // row group
    const int row0 = blockIdx.y * 128;
    const int col0 = blockIdx.x * 64;
    const int M = N_NODES, N = HID, K = IN_DIM;

    float acc[8][4] = {};

    for (int kt = 0; kt < K; kt += 16) {
        #pragma unroll
        for (int l = 0; l < 2; l++) {
            int idx = tid + l * 256;       // 0..511
            int r = idx >> 2;              // 0..127
            int kq = (idx & 3) * 4;
            int row = row0 + r;
            float4 v = (row < M) ? *reinterpret_cast<const float4*>(g_y + (size_t)row * K + kt + kq)
                                 : make_float4(0.f, 0.f, 0.f, 0.f);
            As[kq + 0][r] = v.x; As[kq + 1][r] = v.y;
            As[kq + 2][r] = v.z; As[kq + 3][r] = v.w;
        }
        {
            int k = tid >> 4;
            int cq = (tid & 15) * 4;
            float4 v = *reinterpret_cast<const float4*>(g_Wc + (size_t)(kt + k) * N + col0 + cq);
            *reinterpret_cast<float4*>(&Bs[k][cq]) = v;
        }
        __syncthreads();

        #pragma unroll
        for (int k = 0; k < 16; k++) {
            float a[8];
            float4 a0 = *reinterpret_cast<const float4*>(&As[k][ty * 8]);
            float4 a1 = *reinterpret_cast<const float4*>(&As[k][ty * 8 + 4]);
            a[0] = a0.x; a[1] = a0.y; a[2] = a0.z; a[3] = a0.w;
            a[4] = a1.x; a[5] = a1.y; a[6] = a1.z; a[7] = a1.w;
            float4 b = *reinterpret_cast<const float4*>(&Bs[k][tx * 4]);
            float bv[4] = {b.x, b.y, b.z, b.w};
            #pragma unroll
            for (int i = 0; i < 8; i++)
                #pragma unroll
                for (int j = 0; j < 4; j++)
                    acc[i][j] = fmaf(a[i], bv[j], acc[i][j]);
        }
        __syncthreads();
    }

    const int col = col0 + tx * 4;
    const float4 bc4 = *reinterpret_cast<const float4*>(g_bc + col);
    const float4 bg4 = *reinterpret_cast<const float4*>(bgcn + col);
    #pragma unroll
    for (int i = 0; i < 8; i++) {
        int row = row0 + ty * 8 + i;
        if (row >= M) continue;
        float sc = g_dinv[row];
        float uu = g_u[row];
        float4 v;
        v.x = acc[i][0] * sc + bc4.x * uu + bg4.x;
        v.y = acc[i][1] * sc + bc4.y * uu + bg4.y;
        v.z = acc[i][2] * sc + bc4.z * uu + bg4.z;
        v.w = acc[i][3] * sc + bc4.w * uu + bg4.w;
        *reinterpret_cast<float4*>(out + (size_t)row * N + col) = v;
    }
}

// ---------------- launch ----------------
extern "C" void kernel_launch(void* const* d_in, const int* in_sizes, int n_in,
                              void* d_out, int out_size) {
    const float* x    = (const float*)d_in[0];
    const int*   ei   = (const int*)d_in[1];      // jax int64 is silently int32 (x64 disabled)
    const float* Wp   = (const float*)d_in[2];
    const float* bp   = (const float*)d_in[3];
    const float* W_ih = (const float*)d_in[4];
    const float* W_hh = (const float*)d_in[5];
    const float* b_ih = (const float*)d_in[6];
    const float* b_hh = (const float*)d_in[7];
    const float* IW   = (const float*)d_in[8];
    const float* bgcn = (const float*)d_in[9];
    float* out = (float*)d_out;

    float* d_gates; cudaGetSymbolAddress((void**)&d_gates, g_gates);
    float* d_W;     cudaGetSymbolAddress((void**)&d_W,     g_W);
    float* d_Wc;    cudaGetSymbolAddress((void**)&d_Wc,    g_Wc);

    dim3 thr(16, 16);

    // CSR build + dinv
    k_deg_zero<<<(N_NODES + 255) / 256, 256>>>();
    k_deg_acc<<<(N_EDGES + 255) / 256, 256>>>(ei);
    k_scan<<<1, 1024>>>();
    k_fill<<<(N_EDGES + 255) / 256, 256>>>(ei);

    // y, u aggregation (depends only on CSR + x)
    k_gather<<<(N_NODES * 32 + 255) / 256, 256>>>(x);

    // weight evolution chain
    sgemm<true, true><<<dim3(HID4 / 64, HID / 64), thr>>>(
        IW, W_ih, W_hh, b_ih, b_hh, d_gates, HID, HID4, HID);
    k_evolve<<<(HID * HID + 255) / 256, 256>>>(IW);
    sgemm<false, false><<<dim3(HID / 64, IN_DIM / 64), thr>>>(
        Wp, d_W, nullptr, nullptr, nullptr, d_Wc, IN_DIM, HID, HID);
    k_bc<<<4, 256>>>(bp);

    // out = (y @ Wc)*dinv + bc*u + bgcn
    k_main_gemm<<<dim3(HID / 64, (N_NODES + 127) / 128), 256>>>(bgcn, out);
}

// round 6
// speedup vs baseline: 2.9245x; 1.1955x over previous
#include <cuda_runtime.h>
#include <cuda_bf16.h>

#define N_NODES 10000
#define N_EDGES 320000
#define IN_DIM  128
#define HID     256
#define HID4    1024

// ---------------- scratch (static device globals; no allocation) ----------------
__device__ float g_gates[HID * HID4];   // IW @ (W_ih+W_hh)^T + b_ih + b_hh   [H, 4H]
__device__ float g_W[HID * HID];        // evolved GCN weight                 [H, H]
__device__ float g_Wc[IN_DIM * HID];    // Wp @ W                             [IN, H]
__device__ float g_bc[HID];             // bp @ W                             [H]
__device__ float g_y[N_NODES * IN_DIM]; // aggregated scaled features        [N, IN]
__device__ float g_us[N_NODES];         // sum over in-edges of dinv[src]
__device__ float g_dinv[N_NODES];       // rsqrt(deg+1)
__device__ int   g_deg[N_NODES];

// ---------------- streams for fork/join overlap (created at static init) ----------------
static cudaStream_t g_s2 = nullptr;
static cudaEvent_t g_evFork = nullptr, g_evJoin = nullptr;
namespace {
struct StreamInit {
    StreamInit() {
        cudaStreamCreateWithFlags(&g_s2, cudaStreamNonBlocking);
        cudaEventCreateWithFlags(&g_evFork, cudaEventDisableTiming);
        cudaEventCreateWithFlags(&g_evJoin, cudaEventDisableTiming);
    }
};
static StreamInit g_si;
}

// ---------------- graph prologue ----------------
__global__ void k_zero() {
    int t = blockIdx.x * blockDim.x + threadIdx.x;
    if (t < N_NODES) { g_deg[t] = 0; g_us[t] = 0.0f; }
}

__global__ void k_deg_acc(const int* __restrict__ ei) {
    int e = blockIdx.x * blockDim.x + threadIdx.x;
    if (e < N_EDGES) atomicAdd(&g_deg[ei[N_EDGES + e]], 1);
}

// one warp per node: dinv[n] = rsqrt(deg+1); y[n,:] = x[n,:] * dinv[n]
__global__ void k_node_init(const float4* __restrict__ x4) {
    int n = (blockIdx.x * blockDim.x + threadIdx.x) >> 5;
    int lane = threadIdx.x & 31;
    if (n >= N_NODES) return;
    float di = rsqrtf((float)g_deg[n] + 1.0f);
    if (lane == 0) g_dinv[n] = di;
    float4 v = x4[(size_t)n * 32 + lane];
    reinterpret_cast<float4*>(g_y)[(size_t)n * 32 + lane] =
        make_float4(v.x * di, v.y * di, v.z * di, v.w * di);
}

// one warp per edge: y[d,:] += x[s,:]*dinv[s];  us[d] += dinv[s]
__global__ void k_scatter(const int* __restrict__ ei, const float4* __restrict__ x4) {
    int e = (blockIdx.x * blockDim.x + threadIdx.x) >> 5;
    int lane = threadIdx.x & 31;
    if (e >= N_EDGES) return;
    int s = ei[e];
    int d = ei[N_EDGES + e];
    float ws = g_dinv[s];
    float4 v = x4[(size_t)s * 32 + lane];
    float4* yd = reinterpret_cast<float4*>(g_y) + (size_t)d * 32 + lane;
    asm volatile("red.global.add.v4.f32 [%0], {%1,%2,%3,%4};"
                 :: "l"(yd), "f"(v.x * ws), "f"(v.y * ws), "f"(v.z * ws), "f"(v.w * ws)
                 : "memory");
    if (lane == 0)
        asm volatile("red.global.add.f32 [%0], %1;" :: "l"(g_us + d), "f"(ws) : "memory");
}

// ---------------- weight-evolution elementwise ----------------
__device__ __forceinline__ float tanh_fast(float x) {
    float r;
    asm("tanh.approx.f32 %0, %1;" : "=f"(r) : "f"(x));
    return r;
}
__device__ __forceinline__ float sig_fast(float x) {
    return 0.5f * tanh_fast(0.5f * x) + 0.5f;
}

__global__ void k_evolve(const float* __restrict__ iw) {
    int t = blockIdx.x * blockDim.x + threadIdx.x;   // over H*H
    if (t >= HID * HID) return;
    int r = t >> 8;
    int j = t & (HID - 1);
    const float* gr = g_gates + r * HID4;
    float ig = sig_fast(gr[j]);
    float fg = sig_fast(gr[HID + j]);
    float gg = tanh_fast(gr[2 * HID + j]);
    float og = sig_fast(gr[3 * HID + j]);
    float c = fg * iw[t] + ig * gg;
    g_W[t] = og * tanh_fast(c);
}

// bc[j] = sum_k bp[k] * W[k, j]   (4 blocks x 256 threads)
__global__ void k_bc(const float* __restrict__ bp) {
    __shared__ float red[4][64];
    int c  = threadIdx.x & 63;
    int kk = threadIdx.x >> 6;      // 0..3
    int col = blockIdx.x * 64 + c;
    float acc = 0.0f;
    for (int k = kk; k < HID; k += 4) acc += bp[k] * g_W[k * HID + col];
    red[kk][c] = acc;
    __syncthreads();
    if (kk == 0) g_bc[col] = red[0][c] + red[1][c] + red[2][c] + red[3][c];
}

// ---------------- small tiled fp32 GEMM (weight chain) ----------------
// C[M,N] = A[M,K] @ op(B [+ B2]) + bias [+ bias2].
// TB=false: B is [K,N]. TB=true: B is [N,K]. Requires K%16==0, N%64==0.
template<bool TB, bool FUSEB>
__global__ void sgemm(const float* __restrict__ A, const float* __restrict__ B,
                      const float* __restrict__ B2,
                      const float* __restrict__ bias, const float* __restrict__ bias2,
                      float* __restrict__ C, int M, int N, int K) {
    __shared__ float As[16][68];
    __shared__ float Bs[16][68];
    const int tx = threadIdx.x, ty = threadIdx.y;
    const int tid = ty * 16 + tx;
    const int row0 = blockIdx.y * 64;
    const int col0 = blockIdx.x * 64;

    float acc[4][4] = {};

    for (int kt = 0; kt < K; kt += 16) {
        {
            int r = tid >> 2;
            int kq = (tid & 3) * 4;
            int row = row0 + r;
            float4 v = (row < M) ? *reinterpret_cast<const float4*>(A + (size_t)row * K + kt + kq)
                                 : make_float4(0.f, 0.f, 0.f, 0.f);
            As[kq + 0][r] = v.x; As[kq + 1][r] = v.y;
            As[kq + 2][r] = v.z; As[kq + 3][r] = v.w;
        }
        if (!TB) {
            int k = tid >> 4;
            int cq = (tid & 15) * 4;
            size_t idx = (size_t)(kt + k) * N + col0 + cq;
            float4 v = *reinterpret_cast<const float4*>(B + idx);
            if (FUSEB) {
                float4 w = *reinterpret_cast<const float4*>(B2 + idx);
                v.x += w.x; v.y += w.y; v.z += w.z; v.w += w.w;
            }
            *reinterpret_cast<float4*>(&Bs[k][cq]) = v;
        } else {
            int c = tid >> 2;
            int kq = (tid & 3) * 4;
            size_t idx = (size_t)(col0 + c) * K + kt + kq;
            float4 v = *reinterpret_cast<const float4*>(B + idx);
            if (FUSEB) {
                float4 w = *reinterpret_cast<const float4*>(B2 + idx);
                v.x += w.x; v.y += w.y; v.z += w.z; v.w += w.w;
            }
            Bs[kq + 0][c] = v.x; Bs[kq + 1][c] = v.y;
            Bs[kq + 2][c] = v.z; Bs[kq + 3][c] = v.w;
        }
        __syncthreads();

        #pragma unroll
        for (int k = 0; k < 16; k++) {
            float4 a = *reinterpret_cast<const float4*>(&As[k][ty * 4]);
            float4 b = *reinterpret_cast<const float4*>(&Bs[k][tx * 4]);
            float av[4] = {a.x, a.y, a.z, a.w};
            float bv[4] = {b.x, b.y, b.z, b.w};
            #pragma unroll
            for (int i = 0; i < 4; i++)
                #pragma unroll
                for (int j = 0; j < 4; j++)
                    acc[i][j] = fmaf(av[i], bv[j], acc[i][j]);
        }
        __syncthreads();
    }

    #pragma unroll
    for (int i = 0; i < 4; i++) {
        int row = row0 + ty * 4 + i;
        if (row >= M) continue;
        int col = col0 + tx * 4;
        float4 v = make_float4(acc[i][0], acc[i][1], acc[i][2], acc[i][3]);
        if (bias) {
            const float4 bb = *reinterpret_cast<const float4*>(bias + col);
            v.x += bb.x; v.y += bb.y; v.z += bb.z; v.w += bb.w;
        }
        if (bias2) {
            const float4 bb = *reinterpret_cast<const float4*>(bias2 + col);
            v.x += bb.x; v.y += bb.y; v.z += bb.z; v.w += bb.w;
        }
        *reinterpret_cast<float4*>(C + (size_t)row * N + col) = v;
    }
}

// ---------------- main GEMM: out = (y @ Wc)*dinv + bc*(dinv+us)*dinv + bgcn ----------------
// 128x64 tiles, 8x4 micro-tiles, K = IN_DIM = 128.
__global__ void k_main_gemm(const float* __restrict__ bgcn, float* __restrict__ out) {
    __shared__ float As[16][132];
    __shared__ float Bs[16][68];
    const int tid = threadIdx.x;           // 256 threads
    const int tx = tid & 15;               // col group
    const int ty = tid >> 4;               // row group
    const int row0 = blockIdx.y * 128;
    const int col0 = blockIdx.x * 64;
    const int M = N_NODES, N = HID, K = IN_DIM;

    float acc[8][4] = {};

    for (int kt = 0; kt < K; kt += 16) {
        #pragma unroll
        for (int l = 0; l < 2; l++) {
            int idx = tid + l * 256;       // 0..511
            int r = idx >> 2;              // 0..127
            int kq = (idx & 3) * 4;
            int row = row0 + r;
            float4 v = (row < M) ? *reinterpret_cast<const float4*>(g_y + (size_t)row * K + kt + kq)
                                 : make_float4(0.f, 0.f, 0.f, 0.f);
            As[kq + 0][r] = v.x; As[kq + 1][r] = v.y;
            As[kq + 2][r] = v.z; As[kq + 3][r] = v.w;
        }
        {
            int k = tid >> 4;
            int cq = (tid & 15) * 4;
            float4 v = *reinterpret_cast<const float4*>(g_Wc + (size_t)(kt + k) * N + col0 + cq);
            *reinterpret_cast<float4*>(&Bs[k][cq]) = v;
        }
        __syncthreads();

        #pragma unroll
        for (int k = 0; k < 16; k++) {
            float a[8];
            float4 a0 = *reinterpret_cast<const float4*>(&As[k][ty * 8]);
            float4 a1 = *reinterpret_cast<const float4*>(&As[k][ty * 8 + 4]);
            a[0] = a0.x; a[1] = a0.y; a[2] = a0.z; a[3] = a0.w;
            a[4] = a1.x; a[5] = a1.y; a[6] = a1.z; a[7] = a1.w;
            float4 b = *reinterpret_cast<const float4*>(&Bs[k][tx * 4]);
            float bv[4] = {b.x, b.y, b.z, b.w};
            #pragma unroll
            for (int i = 0; i < 8; i++)
                #pragma unroll
                for (int j = 0; j < 4; j++)
                    acc[i][j] = fmaf(a[i], bv[j], acc[i][j]);
        }
        __syncthreads();
    }

    const int col = col0 + tx * 4;
    const float4 bc4 = *reinterpret_cast<const float4*>(g_bc + col);
    const float4 bg4 = *reinterpret_cast<const float4*>(bgcn + col);
    #pragma unroll
    for (int i = 0; i < 8; i++) {
        int row = row0 + ty * 8 + i;
        if (row >= M) continue;
        float sc = g_dinv[row];
        float uu = (sc + g_us[row]) * sc;
        float4 v;
        v.x = acc[i][0] * sc + bc4.x * uu + bg4.x;
        v.y = acc[i][1] * sc + bc4.y * uu + bg4.y;
        v.z = acc[i][2] * sc + bc4.z * uu + bg4.z;
        v.w = acc[i][3] * sc + bc4.w * uu + bg4.w;
        *reinterpret_cast<float4*>(out + (size_t)row * N + col) = v;
    }
}

// ---------------- launch ----------------
extern "C" void kernel_launch(void* const* d_in, const int* in_sizes, int n_in,
                              void* d_out, int out_size) {
    const float* x    = (const float*)d_in[0];
    const int*   ei   = (const int*)d_in[1];      // jax int64 is silently int32 (x64 disabled)
    const float* Wp   = (const float*)d_in[2];
    const float* bp   = (const float*)d_in[3];
    const float* W_ih = (const float*)d_in[4];
    const float* W_hh = (const float*)d_in[5];
    const float* b_ih = (const float*)d_in[6];
    const float* b_hh = (const float*)d_in[7];
    const float* IW   = (const float*)d_in[8];
    const float* bgcn = (const float*)d_in[9];
    float* out = (float*)d_out;

    float* d_gates; cudaGetSymbolAddress((void**)&d_gates, g_gates);
    float* d_W;     cudaGetSymbolAddress((void**)&d_W,     g_W);
    float* d_Wc;    cudaGetSymbolAddress((void**)&d_Wc,    g_Wc);

    dim3 thr(16, 16);

    // fork: weight-evolution chain on second stream (independent of graph chain)
    cudaEventRecord(g_evFork, 0);
    cudaStreamWaitEvent(g_s2, g_evFork, 0);
    sgemm<true, true><<<dim3(HID4 / 64, HID / 64), thr, 0, g_s2>>>(
        IW, W_ih, W_hh, b_ih, b_hh, d_gates, HID, HID4, HID);
    k_evolve<<<(HID * HID + 255) / 256, 256, 0, g_s2>>>(IW);
    sgemm<false, false><<<dim3(HID / 64, IN_DIM / 64), thr, 0, g_s2>>>(
        Wp, d_W, nullptr, nullptr, nullptr, d_Wc, IN_DIM, HID, HID);
    k_bc<<<4, 256, 0, g_s2>>>(bp);
    cudaEventRecord(g_evJoin, g_s2);

    // graph chain on default stream
    k_zero<<<(N_NODES + 255) / 256, 256>>>();
    k_deg_acc<<<(N_EDGES + 255) / 256, 256>>>(ei);
    k_node_init<<<(N_NODES * 32 + 255) / 256, 256>>>((const float4*)x);
    k_scatter<<<(N_EDGES * 32 + 255) / 256, 256>>>(ei, (const float4*)x);

    // join, then final GEMM
    cudaStreamWaitEvent(0, g_evJoin, 0);
    k_main_gemm<<<dim3(HID / 64, (N_NODES + 127) / 128), 256>>>(bgcn, out);
}

// round 7
// speedup vs baseline: 3.9913x; 1.3648x over previous
#include <cuda_runtime.h>
#include <cuda_bf16.h>

#define N_NODES 10000
#define N_EDGES 320000
#define IN_DIM  128
#define HID     256
#define HID4    1024
#define BKT     192      // bucket capacity: deg ~ Poisson(32), 192 = +28 sigma

// ---------------- scratch (static device globals; no allocation) ----------------
__device__ float g_gates[HID * HID4];   // IW @ (W_ih+W_hh)^T + b_ih + b_hh   [H, 4H]
__device__ float g_W[HID * HID];        // evolved GCN weight                 [H, H]
__device__ float g_Wc[IN_DIM * HID];    // Wp @ W                             [IN, H]
__device__ float g_bc[HID];             // bp @ W                             [H]
__device__ float g_y[N_NODES * IN_DIM]; // aggregated scaled features        [N, IN]
__device__ float g_u[N_NODES];          // dinv[i] + sum_in dinv[s]
__device__ float g_dinv[N_NODES];       // rsqrt(deg+1)
__device__ int   g_cur[N_NODES];        // fill cursor == in-degree after fill
__device__ int   g_bkt[N_NODES * BKT];  // per-dst src buckets

// ---------------- streams for fork/join overlap (created at static init) ----------------
static cudaStream_t g_s2 = nullptr;
static cudaEvent_t g_evFork = nullptr, g_evJoin = nullptr;
namespace {
struct StreamInit {
    StreamInit() {
        cudaStreamCreateWithFlags(&g_s2, cudaStreamNonBlocking);
        cudaEventCreateWithFlags(&g_evFork, cudaEventDisableTiming);
        cudaEventCreateWithFlags(&g_evJoin, cudaEventDisableTiming);
    }
};
static StreamInit g_si;
}

// ---------------- graph prologue ----------------
// 4 edges per thread for atomic-latency hiding
__global__ void k_fill(const int* __restrict__ ei) {
    int e0 = (blockIdx.x * blockDim.x + threadIdx.x) * 4;
    #pragma unroll
    for (int q = 0; q < 4; q++) {
        int e = e0 + q;
        if (e < N_EDGES) {
            int s = ei[e];
            int d = ei[N_EDGES + e];
            int pos = atomicAdd(&g_cur[d], 1);
            if (pos < BKT) g_bkt[d * BKT + pos] = s;
        }
    }
}

__global__ void k_dinv() {
    int n = blockIdx.x * blockDim.x + threadIdx.x;
    if (n < N_NODES) g_dinv[n] = rsqrtf((float)g_cur[n] + 1.0f);
}

// one warp per dst node:
// y[i,:] = x[i,:]*dinv[i] + sum_{s in N(i)} x[s,:]*dinv[s]
// u[i]   = dinv[i] + sum dinv[s]
__global__ void k_gather(const float4* __restrict__ x4) {
    int n = (blockIdx.x * blockDim.x + threadIdx.x) >> 5;
    int lane = threadIdx.x & 31;
    if (n >= N_NODES) return;

    const int deg = min(g_cur[n], BKT);
    const int* bkt = g_bkt + (size_t)n * BKT;

    float di = g_dinv[n];
    float4 xv = x4[(size_t)n * 32 + lane];
    float4 acc = make_float4(xv.x * di, xv.y * di, xv.z * di, xv.w * di);
    float tsum = di;

    for (int c = 0; c < deg; c += 32) {
        int m = min(32, deg - c);
        int idx = 0;
        float dv = 0.0f;
        if (lane < m) {
            idx = bkt[c + lane];
            dv = g_dinv[idx];
        }
        int j = 0;
        for (; j + 4 <= m; j += 4) {
            int s0 = __shfl_sync(0xffffffffu, idx, j);
            int s1 = __shfl_sync(0xffffffffu, idx, j + 1);
            int s2 = __shfl_sync(0xffffffffu, idx, j + 2);
            int s3 = __shfl_sync(0xffffffffu, idx, j + 3);
            float w0 = __shfl_sync(0xffffffffu, dv, j);
            float w1 = __shfl_sync(0xffffffffu, dv, j + 1);
            float w2 = __shfl_sync(0xffffffffu, dv, j + 2);
            float w3 = __shfl_sync(0xffffffffu, dv, j + 3);
            float4 v0 = x4[(size_t)s0 * 32 + lane];
            float4 v1 = x4[(size_t)s1 * 32 + lane];
            float4 v2 = x4[(size_t)s2 * 32 + lane];
            float4 v3 = x4[(size_t)s3 * 32 + lane];
            acc.x = fmaf(v0.x, w0, acc.x); acc.y = fmaf(v0.y, w0, acc.y);
            acc.z = fmaf(v0.z, w0, acc.z); acc.w = fmaf(v0.w, w0, acc.w);
            acc.x = fmaf(v1.x, w1, acc.x); acc.y = fmaf(v1.y, w1, acc.y);
            acc.z = fmaf(v1.z, w1, acc.z); acc.w = fmaf(v1.w, w1, acc.w);
            acc.x = fmaf(v2.x, w2, acc.x); acc.y = fmaf(v2.y, w2, acc.y);
            acc.z = fmaf(v2.z, w2, acc.z); acc.w = fmaf(v2.w, w2, acc.w);
            acc.x = fmaf(v3.x, w3, acc.x); acc.y = fmaf(v3.y, w3, acc.y);
            acc.z = fmaf(v3.z, w3, acc.z); acc.w = fmaf(v3.w, w3, acc.w);
            tsum += w0 + w1 + w2 + w3;
        }
        for (; j < m; j++) {
            int s = __shfl_sync(0xffffffffu, idx, j);
            float ws = __shfl_sync(0xffffffffu, dv, j);
            float4 v = x4[(size_t)s * 32 + lane];
            acc.x = fmaf(v.x, ws, acc.x); acc.y = fmaf(v.y, ws, acc.y);
            acc.z = fmaf(v.z, ws, acc.z); acc.w = fmaf(v.w, ws, acc.w);
            tsum += ws;
        }
    }

    reinterpret_cast<float4*>(g_y)[(size_t)n * 32 + lane] = acc;
    if (lane == 0) g_u[n] = tsum;
}

// ---------------- weight-evolution elementwise ----------------
__device__ __forceinline__ float tanh_fast(float x) {
    float r;
    asm("tanh.approx.f32 %0, %1;" : "=f"(r) : "f"(x));
    return r;
}
__device__ __forceinline__ float sig_fast(float x) {
    return 0.5f * tanh_fast(0.5f * x) + 0.5f;
}

__global__ void k_evolve(const float* __restrict__ iw) {
    int t = blockIdx.x * blockDim.x + threadIdx.x;   // over H*H
    if (t >= HID * HID) return;
    int r = t >> 8;
    int j = t & (HID - 1);
    const float* gr = g_gates + r * HID4;
    float ig = sig_fast(gr[j]);
    float fg = sig_fast(gr[HID + j]);
    float gg = tanh_fast(gr[2 * HID + j]);
    float og = sig_fast(gr[3 * HID + j]);
    float c = fg * iw[t] + ig * gg;
    g_W[t] = og * tanh_fast(c);
}

// bc[j] = sum_k bp[k] * W[k, j]   (16 blocks x 256 threads, 16-way k split)
__global__ void k_bc(const float* __restrict__ bp) {
    __shared__ float red[16][17];
    int c  = threadIdx.x & 15;      // col within block
    int kk = threadIdx.x >> 4;      // 0..15 k-split
    int col = blockIdx.x * 16 + c;
    float acc = 0.0f;
    #pragma unroll
    for (int t = 0; t < 16; t++) {
        int k = kk + t * 16;
        acc += bp[k] * g_W[k * HID + col];
    }
    red[kk][c] = acc;
    __syncthreads();
    if (kk == 0) {
        float s = 0.0f;
        #pragma unroll
        for (int t = 0; t < 16; t++) s += red[t][c];
        g_bc[col] = s;
    }
}

// ---------------- small tiled fp32 GEMM (weight chain) ----------------
template<bool TB, bool FUSEB>
__global__ void sgemm(const float* __restrict__ A, const float* __restrict__ B,
                      const float* __restrict__ B2,
                      const float* __restrict__ bias, const float* __restrict__ bias2,
                      float* __restrict__ C, int M, int N, int K) {
    __shared__ float As[16][68];
    __shared__ float Bs[16][68];
    const int tx = threadIdx.x, ty = threadIdx.y;
    const int tid = ty * 16 + tx;
    const int row0 = blockIdx.y * 64;
    const int col0 = blockIdx.x * 64;

    float acc[4][4] = {};

    for (int kt = 0; kt < K; kt += 16) {
        {
            int r = tid >> 2;
            int kq = (tid & 3) * 4;
            int row = row0 + r;
            float4 v = (row < M) ? *reinterpret_cast<const float4*>(A + (size_t)row * K + kt + kq)
                                 : make_float4(0.f, 0.f, 0.f, 0.f);
            As[kq + 0][r] = v.x; As[kq + 1][r] = v.y;
            As[kq + 2][r] = v.z; As[kq + 3][r] = v.w;
        }
        if (!TB) {
            int k = tid >> 4;
            int cq = (tid & 15) * 4;
            size_t idx = (size_t)(kt + k) * N + col0 + cq;
            float4 v = *reinterpret_cast<const float4*>(B + idx);
            if (FUSEB) {
                float4 w = *reinterpret_cast<const float4*>(B2 + idx);
                v.x += w.x; v.y += w.y; v.z += w.z; v.w += w.w;
            }
            *reinterpret_cast<float4*>(&Bs[k][cq]) = v;
        } else {
            int c = tid >> 2;
            int kq = (tid & 3) * 4;
            size_t idx = (size_t)(col0 + c) * K + kt + kq;
            float4 v = *reinterpret_cast<const float4*>(B + idx);
            if (FUSEB) {
                float4 w = *reinterpret_cast<const float4*>(B2 + idx);
                v.x += w.x; v.y += w.y; v.z += w.z; v.w += w.w;
            }
            Bs[kq + 0][c] = v.x; Bs[kq + 1][c] = v.y;
            Bs[kq + 2][c] = v.z; Bs[kq + 3][c] = v.w;
        }
        __syncthreads();

        #pragma unroll
        for (int k = 0; k < 16; k++) {
            float4 a = *reinterpret_cast<const float4*>(&As[k][ty * 4]);
            float4 b = *reinterpret_cast<const float4*>(&Bs[k][tx * 4]);
            float av[4] = {a.x, a.y, a.z, a.w};
            float bv[4] = {b.x, b.y, b.z, b.w};
            #pragma unroll
            for (int i = 0; i < 4; i++)
                #pragma unroll
                for (int j = 0; j < 4; j++)
                    acc[i][j] = fmaf(av[i], bv[j], acc[i][j]);
        }
        __syncthreads();
    }

    #pragma unroll
    for (int i = 0; i < 4; i++) {
        int row = row0 + ty * 4 + i;
        if (row >= M) continue;
        int col = col0 + tx * 4;
        float4 v = make_float4(acc[i][0], acc[i][1], acc[i][2], acc[i][3]);
        if (bias) {
            const float4 bb = *reinterpret_cast<const float4*>(bias + col);
            v.x += bb.x; v.y += bb.y; v.z += bb.z; v.w += bb.w;
        }
        if (bias2) {
            const float4 bb = *reinterpret_cast<const float4*>(bias2 + col);
            v.x += bb.x; v.y += bb.y; v.z += bb.z; v.w += bb.w;
        }
        *reinterpret_cast<float4*>(C + (size_t)row * N + col) = v;
    }
}

// ---------------- main GEMM (f32x2 packed FMA) ----------------
// out = (y @ Wc)*dinv + bc*u*dinv + bgcn.  128x64 tiles, 8x4 micro-tiles.
__global__ void k_main_gemm(const float* __restrict__ bgcn, float* __restrict__ out) {
    __shared__ float As[16][132];
    __shared__ float Bs[16][68];
    const int tid = threadIdx.x;           // 256 threads
    const int tx = tid & 15;
    const int ty = tid >> 4;
    const int row0 = blockIdx.y * 128;
    const int col0 = blockIdx.x * 64;
    const int M = N_NODES, N = HID, K = IN_DIM;

    // acc2[i2][j]: f32x2 over row pair (ty*8+2*i2, +1), column col0+tx*4+j
    unsigned long long acc2[4][4] = {};

    for (int kt = 0; kt < K; kt += 16) {
        #pragma unroll
        for (int l = 0; l < 2; l++) {
            int idx = tid + l * 256;
            int r = idx >> 2;
            int kq = (idx & 3) * 4;
            int row = row0 + r;
            float4 v = (row < M) ? *reinterpret_cast<const float4*>(g_y + (size_t)row * K + kt + kq)
                                 : make_float4(0.f, 0.f, 0.f, 0.f);
            As[kq + 0][r] = v.x; As[kq + 1][r] = v.y;
            As[kq + 2][r] = v.z; As[kq + 3][r] = v.w;
        }
        {
            int k = tid >> 4;
            int cq = (tid & 15) * 4;
            float4 v = *reinterpret_cast<const float4*>(g_Wc + (size_t)(kt + k) * N + col0 + cq);
            *reinterpret_cast<float4*>(&Bs[k][cq]) = v;
        }
        __syncthreads();

        #pragma unroll
        for (int k = 0; k < 16; k++) {
            // a pairs: consecutive rows in As
            unsigned long long ap[4];
            #pragma unroll
            for (int i2 = 0; i2 < 4; i2++)
                ap[i2] = *reinterpret_cast<const unsigned long long*>(&As[k][ty * 8 + 2 * i2]);
            float4 b = *reinterpret_cast<const float4*>(&Bs[k][tx * 4]);
            unsigned long long bp0, bp1, bp2, bp3;
            asm("mov.b64 %0, {%1, %1};" : "=l"(bp0) : "f"(b.x));
            asm("mov.b64 %0, {%1, %1};" : "=l"(bp1) : "f"(b.y));
            asm("mov.b64 %0, {%1, %1};" : "=l"(bp2) : "f"(b.z));
            asm("mov.b64 %0, {%1, %1};" : "=l"(bp3) : "f"(b.w));
            #pragma unroll
            for (int i2 = 0; i2 < 4; i2++) {
                asm("fma.rn.f32x2 %0, %1, %2, %0;" : "+l"(acc2[i2][0]) : "l"(ap[i2]), "l"(bp0));
                asm("fma.rn.f32x2 %0, %1, %2, %0;" : "+l"(acc2[i2][1]) : "l"(ap[i2]), "l"(bp1));
                asm("fma.rn.f32x2 %0, %1, %2, %0;" : "+l"(acc2[i2][2]) : "l"(ap[i2]), "l"(bp2));
                asm("fma.rn.f32x2 %0, %1, %2, %0;" : "+l"(acc2[i2][3]) : "l"(ap[i2]), "l"(bp3));
            }
        }
        __syncthreads();
    }

    const int col = col0 + tx * 4;
    const float4 bc4 = *reinterpret_cast<const float4*>(g_bc + col);
    const float4 bg4 = *reinterpret_cast<const float4*>(bgcn + col);
    #pragma unroll
    for (int i2 = 0; i2 < 4; i2++) {
        float lo[4], hi[4];
        #pragma unroll
        for (int j = 0; j < 4; j++)
            asm("mov.b64 {%0, %1}, %2;" : "=f"(lo[j]), "=f"(hi[j]) : "l"(acc2[i2][j]));
        #pragma unroll
        for (int h = 0; h < 2; h++) {
            int row = row0 + ty * 8 + 2 * i2 + h;
            if (row >= M) continue;
            float* a = h ? hi : lo;
            float sc = g_dinv[row];
            float uu = g_u[row] * sc;
            float4 v;
            v.x = a[0] * sc + bc4.x * uu + bg4.x;
            v.y = a[1] * sc + bc4.y * uu + bg4.y;
            v.z = a[2] * sc + bc4.z * uu + bg4.z;
            v.w = a[3] * sc + bc4.w * uu + bg4.w;
            *reinterpret_cast<float4*>(out + (size_t)row * N + col) = v;
        }
    }
}

// ---------------- launch ----------------
extern "C" void kernel_launch(void* const* d_in, const int* in_sizes, int n_in,
                              void* d_out, int out_size) {
    const float* x    = (const float*)d_in[0];
    const int*   ei   = (const int*)d_in[1];      // jax int64 is silently int32 (x64 disabled)
    const float* Wp   = (const float*)d_in[2];
    const float* bp   = (const float*)d_in[3];
    const float* W_ih = (const float*)d_in[4];
    const float* W_hh = (const float*)d_in[5];
    const float* b_ih = (const float*)d_in[6];
    const float* b_hh = (const float*)d_in[7];
    const float* IW   = (const float*)d_in[8];
    const float* bgcn = (const float*)d_in[9];
    float* out = (float*)d_out;

    float* d_gates; cudaGetSymbolAddress((void**)&d_gates, g_gates);
    float* d_W;     cudaGetSymbolAddress((void**)&d_W,     g_W);
    float* d_Wc;    cudaGetSymbolAddress((void**)&d_Wc,    g_Wc);
    int*   d_cur;   cudaGetSymbolAddress((void**)&d_cur,   g_cur);

    dim3 thr(16, 16);

    // fork: weight-evolution chain on second stream
    cudaEventRecord(g_evFork, 0);
    cudaStreamWaitEvent(g_s2, g_evFork, 0);
    sgemm<true, true><<<dim3(HID4 / 64, HID / 64), thr, 0, g_s2>>>(
        IW, W_ih, W_hh, b_ih, b_hh, d_gates, HID, HID4, HID);
    k_evolve<<<(HID * HID + 255) / 256, 256, 0, g_s2>>>(IW);
    sgemm<false, false><<<dim3(HID / 64, IN_DIM / 64), thr, 0, g_s2>>>(
        Wp, d_W, nullptr, nullptr, nullptr, d_Wc, IN_DIM, HID, HID);
    k_bc<<<16, 256, 0, g_s2>>>(bp);
    cudaEventRecord(g_evJoin, g_s2);

    // graph chain on default stream
    cudaMemsetAsync(d_cur, 0, N_NODES * sizeof(int), 0);
    k_fill<<<(N_EDGES / 4 + 255) / 256, 256>>>(ei);
    k_dinv<<<(N_NODES + 255) / 256, 256>>>();
    k_gather<<<(N_NODES * 32 + 255) / 256, 256>>>((const float4*)x);

    // join, then final GEMM
    cudaStreamWaitEvent(0, g_evJoin, 0);
    k_main_gemm<<<dim3(HID / 64, (N_NODES + 127) / 128), 256>>>(bgcn, out);
}

// round 8
// speedup vs baseline: 4.1273x; 1.0341x over previous
#include <cuda_runtime.h>
#include <cuda_bf16.h>

#define N_NODES 10000
#define N_EDGES 320000
#define IN_DIM  128
#define HID     256
#define HID4    1024
#define BKT     192      // bucket capacity: deg ~ Poisson(32), 192 = +28 sigma

// ---------------- scratch (static device globals; no allocation) ----------------
__device__ float g_gates[HID * HID4];   // IW @ (W_ih+W_hh)^T + b_ih + b_hh   [H, 4H]
__device__ float g_W[HID * HID];        // evolved GCN weight                 [H, H]
__device__ float g_Wc[IN_DIM * HID];    // Wp @ W                             [IN, H]
__device__ float g_bc[HID];             // bp @ W                             [H]
__device__ float g_y[N_NODES * IN_DIM]; // aggregated scaled features        [N, IN]
__device__ float g_u[N_NODES];          // dinv[i] + sum_in dinv[s]
__device__ int   g_cur[N_NODES];        // fill cursor == in-degree after fill
__device__ int   g_bkt[N_NODES * BKT];  // per-dst src buckets

// ---------------- streams for fork/join overlap (created at static init) ----------------
static cudaStream_t g_s2 = nullptr;
static cudaEvent_t g_evFork = nullptr, g_evJoin = nullptr;
namespace {
struct StreamInit {
    StreamInit() {
        cudaStreamCreateWithFlags(&g_s2, cudaStreamNonBlocking);
        cudaEventCreateWithFlags(&g_evFork, cudaEventDisableTiming);
        cudaEventCreateWithFlags(&g_evJoin, cudaEventDisableTiming);
    }
};
static StreamInit g_si;
}

__device__ __forceinline__ float dinv_of(int cur) {
    return rsqrtf((float)cur + 1.0f);
}

// ---------------- graph prologue ----------------
// 4 edges per thread, vectorized loads
__global__ void k_fill(const int* __restrict__ ei) {
    int t = blockIdx.x * blockDim.x + threadIdx.x;
    if (t >= N_EDGES / 4) return;
    int4 s4 = *reinterpret_cast<const int4*>(ei + t * 4);
    int4 d4 = *reinterpret_cast<const int4*>(ei + N_EDGES + t * 4);
    int s[4] = {s4.x, s4.y, s4.z, s4.w};
    int d[4] = {d4.x, d4.y, d4.z, d4.w};
    #pragma unroll
    for (int q = 0; q < 4; q++) {
        int pos = atomicAdd(&g_cur[d[q]], 1);
        if (pos < BKT) g_bkt[d[q] * BKT + pos] = s[q];
    }
}

// one warp per dst node:
// y[i,:] = x[i,:]*dinv[i] + sum_{s in N(i)} x[s,:]*dinv[s]
// u[i]   = dinv[i] + sum dinv[s]      (dinv computed on the fly from g_cur)
__global__ void k_gather(const float4* __restrict__ x4) {
    int n = (blockIdx.x * blockDim.x + threadIdx.x) >> 5;
    int lane = threadIdx.x & 31;
    if (n >= N_NODES) return;

    const int deg = min(g_cur[n], BKT);
    const int* bkt = g_bkt + (size_t)n * BKT;

    float di = dinv_of(deg);
    float4 xv = __ldg(x4 + (size_t)n * 32 + lane);
    float4 acc = make_float4(xv.x * di, xv.y * di, xv.z * di, xv.w * di);
    float tsum = di;

    for (int c = 0; c < deg; c += 32) {
        int m = min(32, deg - c);
        int idx = 0;
        float dv = 0.0f;
        if (lane < m) {
            idx = __ldg(bkt + c + lane);
            dv = dinv_of(__ldg(g_cur + idx));
        }
        int j = 0;
        for (; j + 4 <= m; j += 4) {
            int s0 = __shfl_sync(0xffffffffu, idx, j);
            int s1 = __shfl_sync(0xffffffffu, idx, j + 1);
            int s2 = __shfl_sync(0xffffffffu, idx, j + 2);
            int s3 = __shfl_sync(0xffffffffu, idx, j + 3);
            float w0 = __shfl_sync(0xffffffffu, dv, j);
            float w1 = __shfl_sync(0xffffffffu, dv, j + 1);
            float w2 = __shfl_sync(0xffffffffu, dv, j + 2);
            float w3 = __shfl_sync(0xffffffffu, dv, j + 3);
            float4 v0 = __ldg(x4 + (size_t)s0 * 32 + lane);
            float4 v1 = __ldg(x4 + (size_t)s1 * 32 + lane);
            float4 v2 = __ldg(x4 + (size_t)s2 * 32 + lane);
            float4 v3 = __ldg(x4 + (size_t)s3 * 32 + lane);
            acc.x = fmaf(v0.x, w0, acc.x); acc.y = fmaf(v0.y, w0, acc.y);
            acc.z = fmaf(v0.z, w0, acc.z); acc.w = fmaf(v0.w, w0, acc.w);
            acc.x = fmaf(v1.x, w1, acc.x); acc.y = fmaf(v1.y, w1, acc.y);
            acc.z = fmaf(v1.z, w1, acc.z); acc.w = fmaf(v1.w, w1, acc.w);
            acc.x = fmaf(v2.x, w2, acc.x); acc.y = fmaf(v2.y, w2, acc.y);
            acc.z = fmaf(v2.z, w2, acc.z); acc.w = fmaf(v2.w, w2, acc.w);
            acc.x = fmaf(v3.x, w3, acc.x); acc.y = fmaf(v3.y, w3, acc.y);
            acc.z = fmaf(v3.z, w3, acc.z); acc.w = fmaf(v3.w, w3, acc.w);
            tsum += w0 + w1 + w2 + w3;
        }
        for (; j < m; j++) {
            int s = __shfl_sync(0xffffffffu, idx, j);
            float ws = __shfl_sync(0xffffffffu, dv, j);
            float4 v = __ldg(x4 + (size_t)s * 32 + lane);
            acc.x = fmaf(v.x, ws, acc.x); acc.y = fmaf(v.y, ws, acc.y);
            acc.z = fmaf(v.z, ws, acc.z); acc.w = fmaf(v.w, ws, acc.w);
            tsum += ws;
        }
    }

    reinterpret_cast<float4*>(g_y)[(size_t)n * 32 + lane] = acc;
    if (lane == 0) g_u[n] = tsum;
}

// ---------------- weight-evolution elementwise ----------------
__device__ __forceinline__ float tanh_fast(float x) {
    float r;
    asm("tanh.approx.f32 %0, %1;" : "=f"(r) : "f"(x));
    return r;
}
__device__ __forceinline__ float sig_fast(float x) {
    return 0.5f * tanh_fast(0.5f * x) + 0.5f;
}

__global__ void k_evolve(const float* __restrict__ iw) {
    int t = blockIdx.x * blockDim.x + threadIdx.x;   // over H*H
    if (t >= HID * HID) return;
    int r = t >> 8;
    int j = t & (HID - 1);
    const float* gr = g_gates + r * HID4;
    float ig = sig_fast(gr[j]);
    float fg = sig_fast(gr[HID + j]);
    float gg = tanh_fast(gr[2 * HID + j]);
    float og = sig_fast(gr[3 * HID + j]);
    float c = fg * iw[t] + ig * gg;
    g_W[t] = og * tanh_fast(c);
}

// bc[j] = sum_k bp[k] * W[k, j]   (16 blocks x 256 threads, 16-way k split)
__global__ void k_bc(const float* __restrict__ bp) {
    __shared__ float red[16][17];
    int c  = threadIdx.x & 15;
    int kk = threadIdx.x >> 4;
    int col = blockIdx.x * 16 + c;
    float acc = 0.0f;
    #pragma unroll
    for (int t = 0; t < 16; t++) {
        int k = kk + t * 16;
        acc += bp[k] * g_W[k * HID + col];
    }
    red[kk][c] = acc;
    __syncthreads();
    if (kk == 0) {
        float s = 0.0f;
        #pragma unroll
        for (int t = 0; t < 16; t++) s += red[t][c];
        g_bc[col] = s;
    }
}

// ---------------- small tiled fp32 GEMM (weight chain) ----------------
template<bool TB, bool FUSEB>
__global__ void sgemm(const float* __restrict__ A, const float* __restrict__ B,
                      const float* __restrict__ B2,
                      const float* __restrict__ bias, const float* __restrict__ bias2,
                      float* __restrict__ C, int M, int N, int K) {
    __shared__ float As[16][68];
    __shared__ float Bs[16][68];
    const int tx = threadIdx.x, ty = threadIdx.y;
    const int tid = ty * 16 + tx;
    const int row0 = blockIdx.y * 64;
    const int col0 = blockIdx.x * 64;

    float acc[4][4] = {};

    for (int kt = 0; kt < K; kt += 16) {
        {
            int r = tid >> 2;
            int kq = (tid & 3) * 4;
            int row = row0 + r;
            float4 v = (row < M) ? *reinterpret_cast<const float4*>(A + (size_t)row * K + kt + kq)
                                 : make_float4(0.f, 0.f, 0.f, 0.f);
            As[kq + 0][r] = v.x; As[kq + 1][r] = v.y;
            As[kq + 2][r] = v.z; As[kq + 3][r] = v.w;
        }
        if (!TB) {
            int k = tid >> 4;
            int cq = (tid & 15) * 4;
            size_t idx = (size_t)(kt + k) * N + col0 + cq;
            float4 v = *reinterpret_cast<const float4*>(B + idx);
            if (FUSEB) {
                float4 w = *reinterpret_cast<const float4*>(B2 + idx);
                v.x += w.x; v.y += w.y; v.z += w.z; v.w += w.w;
            }
            *reinterpret_cast<float4*>(&Bs[k][cq]) = v;
        } else {
            int c = tid >> 2;
            int kq = (tid & 3) * 4;
            size_t idx = (size_t)(col0 + c) * K + kt + kq;
            float4 v = *reinterpret_cast<const float4*>(B + idx);
            if (FUSEB) {
                float4 w = *reinterpret_cast<const float4*>(B2 + idx);
                v.x += w.x; v.y += w.y; v.z += w.z; v.w += w.w;
            }
            Bs[kq + 0][c] = v.x; Bs[kq + 1][c] = v.y;
            Bs[kq + 2][c] = v.z; Bs[kq + 3][c] = v.w;
        }
        __syncthreads();

        #pragma unroll
        for (int k = 0; k < 16; k++) {
            float4 a = *reinterpret_cast<const float4*>(&As[k][ty * 4]);
            float4 b = *reinterpret_cast<const float4*>(&Bs[k][tx * 4]);
            float av[4] = {a.x, a.y, a.z, a.w};
            float bv[4] = {b.x, b.y, b.z, b.w};
            #pragma unroll
            for (int i = 0; i < 4; i++)
                #pragma unroll
                for (int j = 0; j < 4; j++)
                    acc[i][j] = fmaf(av[i], bv[j], acc[i][j]);
        }
        __syncthreads();
    }

    #pragma unroll
    for (int i = 0; i < 4; i++) {
        int row = row0 + ty * 4 + i;
        if (row >= M) continue;
        int col = col0 + tx * 4;
        float4 v = make_float4(acc[i][0], acc[i][1], acc[i][2], acc[i][3]);
        if (bias) {
            const float4 bb = *reinterpret_cast<const float4*>(bias + col);
            v.x += bb.x; v.y += bb.y; v.z += bb.z; v.w += bb.w;
        }
        if (bias2) {
            const float4 bb = *reinterpret_cast<const float4*>(bias2 + col);
            v.x += bb.x; v.y += bb.y; v.z += bb.z; v.w += bb.w;
        }
        *reinterpret_cast<float4*>(C + (size_t)row * N + col) = v;
    }
}

// ---------------- main GEMM (f32x2 packed FMA) ----------------
// out = (y @ Wc)*dinv + bc*u*dinv + bgcn.  128x64 tiles, 8x4 micro-tiles.
__global__ void k_main_gemm(const float* __restrict__ bgcn, float* __restrict__ out) {
    __shared__ float As[16][132];
    __shared__ float Bs[16][68];
    const int tid = threadIdx.x;           // 256 threads
    const int tx = tid & 15;
    const int ty = tid >> 4;
    const int row0 = blockIdx.y * 128;
    const int col0 = blockIdx.x * 64;
    const int M = N_NODES, N = HID, K = IN_DIM;

    unsigned long long acc2[4][4] = {};

    for (int kt = 0; kt < K; kt += 16) {
        #pragma unroll
        for (int l = 0; l < 2; l++) {
            int idx = tid + l * 256;
            int r = idx >> 2;
            int kq = (idx & 3) * 4;
            int row = row0 + r;
            float4 v = (row < M) ? *reinterpret_cast<const float4*>(g_y + (size_t)row * K + kt + kq)
                                 : make_float4(0.f, 0.f, 0.f, 0.f);
            As[kq + 0][r] = v.x; As[kq + 1][r] = v.y;
            As[kq + 2][r] = v.z; As[kq + 3][r] = v.w;
        }
        {
            int k = tid >> 4;
            int cq = (tid & 15) * 4;
            float4 v = *reinterpret_cast<const float4*>(g_Wc + (size_t)(kt + k) * N + col0 + cq);
            *reinterpret_cast<float4*>(&Bs[k][cq]) = v;
        }
        __syncthreads();

        #pragma unroll
        for (int k = 0; k < 16; k++) {
            unsigned long long ap[4];
            #pragma unroll
            for (int i2 = 0; i2 < 4; i2++)
                ap[i2] = *reinterpret_cast<const unsigned long long*>(&As[k][ty * 8 + 2 * i2]);
            float4 b = *reinterpret_cast<const float4*>(&Bs[k][tx * 4]);
            unsigned long long bp0, bp1, bp2, bp3;
            asm("mov.b64 %0, {%1, %1};" : "=l"(bp0) : "f"(b.x));
            asm("mov.b64 %0, {%1, %1};" : "=l"(bp1) : "f"(b.y));
            asm("mov.b64 %0, {%1, %1};" : "=l"(bp2) : "f"(b.z));
            asm("mov.b64 %0, {%1, %1};" : "=l"(bp3) : "f"(b.w));
            #pragma unroll
            for (int i2 = 0; i2 < 4; i2++) {
                asm("fma.rn.f32x2 %0, %1, %2, %0;" : "+l"(acc2[i2][0]) : "l"(ap[i2]), "l"(bp0));
                asm("fma.rn.f32x2 %0, %1, %2, %0;" : "+l"(acc2[i2][1]) : "l"(ap[i2]), "l"(bp1));
                asm("fma.rn.f32x2 %0, %1, %2, %0;" : "+l"(acc2[i2][2]) : "l"(ap[i2]), "l"(bp2));
                asm("fma.rn.f32x2 %0, %1, %2, %0;" : "+l"(acc2[i2][3]) : "l"(ap[i2]), "l"(bp3));
            }
        }
        __syncthreads();
    }

    const int col = col0 + tx * 4;
    const float4 bc4 = *reinterpret_cast<const float4*>(g_bc + col);
    const float4 bg4 = *reinterpret_cast<const float4*>(bgcn + col);
    #pragma unroll
    for (int i2 = 0; i2 < 4; i2++) {
        float lo[4], hi[4];
        #pragma unroll
        for (int j = 0; j < 4; j++)
            asm("mov.b64 {%0, %1}, %2;" : "=f"(lo[j]), "=f"(hi[j]) : "l"(acc2[i2][j]));
        #pragma unroll
        for (int h = 0; h < 2; h++) {
            int row = row0 + ty * 8 + 2 * i2 + h;
            if (row >= M) continue;
            float* a = h ? hi : lo;
            float sc = dinv_of(min(g_cur[row], BKT));
            float uu = g_u[row] * sc;
            float4 v;
            v.x = a[0] * sc + bc4.x * uu + bg4.x;
            v.y = a[1] * sc + bc4.y * uu + bg4.y;
            v.z = a[2] * sc + bc4.z * uu + bg4.z;
            v.w = a[3] * sc + bc4.w * uu + bg4.w;
            *reinterpret_cast<float4*>(out + (size_t)row * N + col) = v;
        }
    }
}

// ---------------- launch ----------------
extern "C" void kernel_launch(void* const* d_in, const int* in_sizes, int n_in,
                              void* d_out, int out_size) {
    const float* x    = (const float*)d_in[0];
    const int*   ei   = (const int*)d_in[1];      // jax int64 is silently int32 (x64 disabled)
    const float* Wp   = (const float*)d_in[2];
    const float* bp   = (const float*)d_in[3];
    const float* W_ih = (const float*)d_in[4];
    const float* W_hh = (const float*)d_in[5];
    const float* b_ih = (const float*)d_in[6];
    const float* b_hh = (const float*)d_in[7];
    const float* IW   = (const float*)d_in[8];
    const float* bgcn = (const float*)d_in[9];
    float* out = (float*)d_out;

    float* d_gates; cudaGetSymbolAddress((void**)&d_gates, g_gates);
    float* d_W;     cudaGetSymbolAddress((void**)&d_W,     g_W);
    float* d_Wc;    cudaGetSymbolAddress((void**)&d_Wc,    g_Wc);
    int*   d_cur;   cudaGetSymbolAddress((void**)&d_cur,   g_cur);

    dim3 thr(16, 16);

    // fork: weight-evolution chain on second stream
    cudaEventRecord(g_evFork, 0);
    cudaStreamWaitEvent(g_s2, g_evFork, 0);
    sgemm<true, true><<<dim3(HID4 / 64, HID / 64), thr, 0, g_s2>>>(
        IW, W_ih, W_hh, b_ih, b_hh, d_gates, HID, HID4, HID);
    k_evolve<<<(HID * HID + 255) / 256, 256, 0, g_s2>>>(IW);
    sgemm<false, false><<<dim3(HID / 64, IN_DIM / 64), thr, 0, g_s2>>>(
        Wp, d_W, nullptr, nullptr, nullptr, d_Wc, IN_DIM, HID, HID);
    k_bc<<<16, 256, 0, g_s2>>>(bp);
    cudaEventRecord(g_evJoin, g_s2);

    // graph chain on default stream
    cudaMemsetAsync(d_cur, 0, N_NODES * sizeof(int), 0);
    k_fill<<<(N_EDGES / 4 + 255) / 256, 256>>>(ei);
    k_gather<<<(N_NODES * 32 + 255) / 256, 256>>>((const float4*)x);

    // join, then final GEMM
    cudaStreamWaitEvent(0, g_evJoin, 0);
    k_main_gemm<<<dim3(HID / 64, (N_NODES + 127) / 128), 256>>>(bgcn, out);
}